// round 7
// baseline (speedup 1.0000x reference)
#include <cuda_runtime.h>
#include <math.h>

// Problem constants: shape (4, 31, 128, 128) fp32
#define HW      128
#define IPIX    (HW * HW)          // 16384
#define NIMG    124                // 4*31
#define NPIX    (NIMG * IPIX)      // 2031616
#define PITCHB  129                // padded pitch for SMEM work buffers
#define LAM_C   0.1f
#define ITERS   20

// ---------------- persistent device state (no allocations allowed) ----------------
__device__ float d_Z[NPIX];
__device__ float d_R[NPIX];
__device__ float d_G1[NPIX];
__device__ float d_G21[2][NPIX];
__device__ float d_G22[2][NPIX];
__device__ float d_Uh[2][NPIX];
__device__ float d_Uv[2][NPIX];
__device__ float d_Hmat[IPIX];     // Hartley matrix (symmetric, orthogonal, H^2 = I)
__device__ float d_lam[HW];        // eigenvalues of 1D circulant D^T D: 2 - 2cos(2*pi*k/128)

__device__ __forceinline__ float shrinkf(float x, float t) {
    float m = fabsf(x) - t;
    m = m > 0.f ? m : 0.f;
    return copysignf(m, x);
}

// ---------------- init: build H, lambda, zero dual state ----------------
__global__ void init_k() {
    int idx = blockIdx.x * blockDim.x + threadIdx.x;
    if (idx < NPIX) {
        d_G1[idx] = 0.f;
        d_G21[0][idx] = 0.f;
        d_G22[0][idx] = 0.f;
    }
    if (idx < IPIX) {
        int a = idx >> 7, b = idx & 127;
        int t = (a * b) & 127;                       // cas is 2*pi periodic
        double ang = (double)t * 0.04908738521234052; // pi/64 = 2*pi/128
        double s = sin(ang), c = cos(ang);
        d_Hmat[idx] = (float)((s + c) * 0.08838834764831845); // 1/sqrt(128)
    }
    if (idx < HW) {
        double ang = (double)idx * 0.04908738521234052;
        d_lam[idx] = (float)(2.0 - 2.0 * cos(ang));
    }
}

// ---------------- pre of iteration 0 (state: Z=X=Y, G=0) ----------------
__global__ void pre0_k(const float* __restrict__ Y, float mu) {
    int p = blockIdx.x * blockDim.x + threadIdx.x;
    if (p >= NPIX) return;
    int base = p & ~(IPIX - 1);
    int rem  = p & (IPIX - 1);
    int i = rem >> 7, j = rem & 127;
    int jw = (j + 127) & 127, je = (j + 1) & 127;
    int in_ = (i + 127) & 127, is = (i + 1) & 127;

    float y  = Y[p];
    float yw = Y[base + i * HW + jw];
    float yn = Y[base + in_ * HW + j];
    float ye = Y[base + i * HW + je];
    float ys = Y[base + is * HW + j];

    float thr = LAM_C / mu;
    float uh   = shrinkf(y - yw, thr);
    float uv   = shrinkf(y - yn, thr);
    float uh_e = shrinkf(ye - y, thr);
    float uv_s = shrinkf(ys - y, thr);

    d_Uh[0][p] = uh;
    d_Uv[0][p] = uv;
    // R = mu1*A + mu2*(Dh^T B + Dv^T C), with A=Y(=X+G1/mu1), B=Uh, C=Uv (G=0)
    d_R[p] = mu * y + mu * ((uh - uh_e) + (uv - uv_s));
}

// ---------------- fused: post of body t-1 + pre of body t ----------------
// mup = mu at body t-1, muc = mu at body t (= rho*mup). po = ping-pong parity (old side).
__global__ void fused_k(const float* __restrict__ Y, const float* __restrict__ Wt,
                        float mup, float muc, int po) {
    int p = blockIdx.x * blockDim.x + threadIdx.x;
    if (p >= NPIX) return;
    int base = p & ~(IPIX - 1);
    int rem  = p & (IPIX - 1);
    int i = rem >> 7, j = rem & 127;
    int jw = (j + 127) & 127, je = (j + 1) & 127;
    int in_ = (i + 127) & 127, is = (i + 1) & 127;
    int pe = base + i * HW + je;     // east
    int ps = base + is * HW + j;     // south

    const float* __restrict__ G21o = d_G21[po];
    const float* __restrict__ G22o = d_G22[po];
    const float* __restrict__ Uho  = d_Uh[po];
    const float* __restrict__ Uvo  = d_Uv[po];
    float* __restrict__ G21n = d_G21[po ^ 1];
    float* __restrict__ G22n = d_G22[po ^ 1];
    float* __restrict__ Uhn  = d_Uh[po ^ 1];
    float* __restrict__ Uvn  = d_Uv[po ^ 1];

    float z  = d_Z[p];
    float zw = d_Z[base + i * HW + jw];
    float zn = d_Z[base + in_ * HW + j];
    float ze = d_Z[pe];
    float zs = d_Z[ps];

    float w  = Wt[p];
    float y  = Y[p];
    float g1 = d_G1[p];

    // ---- post of body t-1 (uses mup) ----
    float xn  = (w * y + mup * z - g1) / (w + mup);
    float g1n = g1 + mup * (xn - z);
    float dh  = z - zw;
    float dv  = z - zn;
    float g21 = G21o[p] + mup * (Uho[p] - dh);
    float g22 = G22o[p] + mup * (Uvo[p] - dv);

    // ---- pre of body t (uses muc) ----
    float thr  = LAM_C / muc;
    float inv2 = 1.0f / muc;
    float uh = shrinkf(dh - g21 * inv2, thr);
    float uv = shrinkf(dv - g22 * inv2, thr);

    // recompute east pixel's (G21', Uh') pointwise to form Bf(i,j+1)
    float dh_e  = ze - z;
    float g21e  = G21o[pe] + mup * (Uho[pe] - dh_e);
    float uh_e  = shrinkf(dh_e - g21e * inv2, thr);
    // recompute south pixel's (G22', Uv') for Cf(i+1,j)
    float dv_s  = zs - z;
    float g22s  = G22o[ps] + mup * (Uvo[ps] - dv_s);
    float uv_s  = shrinkf(dv_s - g22s * inv2, thr);

    float bf   = muc * uh   + g21;
    float bf_e = muc * uh_e + g21e;
    float cf   = muc * uv   + g22;
    float cf_s = muc * uv_s + g22s;

    d_G1[p]  = g1n;
    G21n[p]  = g21;
    G22n[p]  = g22;
    Uhn[p]   = uh;
    Uvn[p]   = uv;
    d_R[p] = muc * xn + g1n + (bf - bf_e) + (cf - cf_s);
}

// ---------------- solve: Z = H [ (H R H) ./ D ] H via 4 in-SMEM GEMMs ----------------
// GEMM convention: out[m][n] = sum_k A[k*PA + m] * B[k*PB + n]
// Thread (ty,tx) in 16x16; register tile strided: m = 16*ii+ty, n = 16*jj+tx (conflict-free LDS).
template <int PA, int PB>
__device__ __forceinline__ void mm128(const float* __restrict__ A,
                                      const float* __restrict__ B,
                                      float acc[8][8], int ty, int tx) {
#pragma unroll
    for (int ii = 0; ii < 8; ii++)
#pragma unroll
        for (int jj = 0; jj < 8; jj++) acc[ii][jj] = 0.f;
#pragma unroll 2
    for (int k = 0; k < 128; k++) {
        float a[8], b[8];
#pragma unroll
        for (int ii = 0; ii < 8; ii++) a[ii] = A[k * PA + ii * 16 + ty];
#pragma unroll
        for (int jj = 0; jj < 8; jj++) b[jj] = B[k * PB + jj * 16 + tx];
#pragma unroll
        for (int ii = 0; ii < 8; ii++)
#pragma unroll
            for (int jj = 0; jj < 8; jj++)
                acc[ii][jj] = fmaf(a[ii], b[jj], acc[ii][jj]);
    }
}

__global__ void __launch_bounds__(256, 1)
solve_k(float* __restrict__ outp, int toOut, float mu1, float mu2) {
    extern __shared__ float sm[];
    float* Hs   = sm;                    // 16384 floats (pitch 128)
    float* lamS = sm + IPIX;             // 128
    float* b0   = sm + IPIX + 128;       // 128*129
    float* b1   = b0 + HW * PITCHB;      // 128*129

    int tid = threadIdx.x;
    int ty = tid >> 4, tx = tid & 15;
    int base = blockIdx.x * IPIX;

    for (int k = tid; k < IPIX; k += 256) Hs[k] = d_Hmat[k];
    if (tid < HW) lamS[tid] = d_lam[tid];
    for (int k = tid; k < IPIX; k += 256) {
        int r = k >> 7, c = k & 127;
        b0[r * PITCHB + c] = d_R[base + k];
    }
    __syncthreads();

    float acc[8][8];

    // G1: T1[u][j] = sum_i H[i][u] * R[i][j]  -> store transposed b1[j][u]
    mm128<HW, PITCHB>(Hs, b0, acc, ty, tx);
#pragma unroll
    for (int ii = 0; ii < 8; ii++)
#pragma unroll
        for (int jj = 0; jj < 8; jj++)
            b1[(jj * 16 + tx) * PITCHB + (ii * 16 + ty)] = acc[ii][jj];
    __syncthreads();

    // G2: T2[u][v] = sum_j T1t[j][u] * H[j][v]; divide by denom -> b0[u][v]
    mm128<PITCHB, HW>(b1, Hs, acc, ty, tx);
    {
        float la[8];
#pragma unroll
        for (int ii = 0; ii < 8; ii++) la[ii] = lamS[ii * 16 + ty];
#pragma unroll
        for (int jj = 0; jj < 8; jj++) {
            float lb = lamS[jj * 16 + tx];
#pragma unroll
            for (int ii = 0; ii < 8; ii++) {
                float den = mu1 + mu2 * (la[ii] + lb);
                b0[(ii * 16 + ty) * PITCHB + (jj * 16 + tx)] = acc[ii][jj] / den;
            }
        }
    }
    __syncthreads();

    // G3: T3[i][v] = sum_u H[u][i] * Zh[u][v] -> store transposed b1[v][i]
    mm128<HW, PITCHB>(Hs, b0, acc, ty, tx);
#pragma unroll
    for (int ii = 0; ii < 8; ii++)
#pragma unroll
        for (int jj = 0; jj < 8; jj++)
            b1[(jj * 16 + tx) * PITCHB + (ii * 16 + ty)] = acc[ii][jj];
    __syncthreads();

    // G4: Z[i][j] = sum_v T3t[v][i] * H[v][j] -> global
    mm128<PITCHB, HW>(b1, Hs, acc, ty, tx);
    float* dst = toOut ? outp : d_Z;
#pragma unroll
    for (int ii = 0; ii < 8; ii++)
#pragma unroll
        for (int jj = 0; jj < 8; jj++)
            dst[base + (ii * 16 + ty) * HW + (jj * 16 + tx)] = acc[ii][jj];
}

// ---------------- launcher ----------------
extern "C" void kernel_launch(void* const* d_in, const int* in_sizes, int n_in,
                              void* d_out, int out_size) {
    const float* Y  = (const float*)d_in[0];
    const float* Wt = (const float*)d_in[1];
    float* outp = (float*)d_out;
    (void)in_sizes; (void)n_in; (void)out_size;

    const size_t shbytes = (size_t)(IPIX + 128 + 2 * HW * PITCHB) * sizeof(float); // 198144
    cudaFuncSetAttribute(solve_k, cudaFuncAttributeMaxDynamicSharedMemorySize, (int)shbytes);

    const int EB = 256;
    const int EG = NPIX / EB;   // 7936

    init_k<<<EG, EB>>>();

    float mu = 0.1f;            // MU1 == MU2 at every step (same init, same rho)
    pre0_k<<<EG, EB>>>(Y, mu);
    solve_k<<<NIMG, 256, shbytes>>>(outp, 0, mu, mu);

    for (int t = 1; t < ITERS; t++) {
        float mup = mu;
        mu = mu * 1.05f;        // matches reference fp32 mu update
        fused_k<<<EG, EB>>>(Y, Wt, mup, mu, (t - 1) & 1);
        solve_k<<<NIMG, 256, shbytes>>>(outp, (t == ITERS - 1) ? 1 : 0, mu, mu);
    }
}

// round 9
// speedup vs baseline: 1.0007x; 1.0007x over previous
#include <cuda_runtime.h>
#include <math.h>

// Problem constants: shape (4, 31, 128, 128) fp32
#define HW      128
#define IPIX    (HW * HW)          // 16384
#define NIMG    124                // 4*31
#define NPIX    (NIMG * IPIX)      // 2031616
#define PITCHB  129                // padded pitch for SMEM work buffers
#define LAM_C   0.1f
#define ITERS   20

// ---------------- persistent device state (no allocations allowed) ----------------
__device__ float d_Z[NPIX];
__device__ float d_R[NPIX];
__device__ float d_G1[NPIX];
__device__ float d_G21[2][NPIX];
__device__ float d_G22[2][NPIX];
__device__ float d_Uh[2][NPIX];
__device__ float d_Uv[2][NPIX];
__device__ float d_Hmat[IPIX];     // Hartley matrix (symmetric, orthogonal, H^2 = I)
__device__ float d_lam[HW];        // eigenvalues of 1D circulant D^T D: 2 - 2cos(2*pi*k/128)

__device__ __forceinline__ float shrinkf(float x, float t) {
    float m = fabsf(x) - t;
    m = m > 0.f ? m : 0.f;
    return copysignf(m, x);
}

// ---------------- init: build H, lambda, zero dual state ----------------
__global__ void init_k() {
    int idx = blockIdx.x * blockDim.x + threadIdx.x;
    if (idx < NPIX) {
        d_G1[idx] = 0.f;
        d_G21[0][idx] = 0.f;
        d_G22[0][idx] = 0.f;
    }
    if (idx < IPIX) {
        int a = idx >> 7, b = idx & 127;
        int t = (a * b) & 127;                       // cas is 2*pi periodic
        double ang = (double)t * 0.04908738521234052; // pi/64 = 2*pi/128
        double s = sin(ang), c = cos(ang);
        d_Hmat[idx] = (float)((s + c) * 0.08838834764831845); // 1/sqrt(128)
    }
    if (idx < HW) {
        double ang = (double)idx * 0.04908738521234052;
        d_lam[idx] = (float)(2.0 - 2.0 * cos(ang));
    }
}

// ---------------- pre of iteration 0 (state: Z=X=Y, G=0) ----------------
__global__ void pre0_k(const float* __restrict__ Y, float mu) {
    int p = blockIdx.x * blockDim.x + threadIdx.x;
    if (p >= NPIX) return;
    int base = p & ~(IPIX - 1);
    int rem  = p & (IPIX - 1);
    int i = rem >> 7, j = rem & 127;
    int jw = (j + 127) & 127, je = (j + 1) & 127;
    int in_ = (i + 127) & 127, is = (i + 1) & 127;

    float y  = Y[p];
    float yw = Y[base + i * HW + jw];
    float yn = Y[base + in_ * HW + j];
    float ye = Y[base + i * HW + je];
    float ys = Y[base + is * HW + j];

    float thr = LAM_C / mu;
    float uh   = shrinkf(y - yw, thr);
    float uv   = shrinkf(y - yn, thr);
    float uh_e = shrinkf(ye - y, thr);
    float uv_s = shrinkf(ys - y, thr);

    d_Uh[0][p] = uh;
    d_Uv[0][p] = uv;
    // R = mu1*A + mu2*(Dh^T B + Dv^T C), with A=Y(=X+G1/mu1), B=Uh, C=Uv (G=0)
    d_R[p] = mu * y + mu * ((uh - uh_e) + (uv - uv_s));
}

// ---------------- fused: post of body t-1 + pre of body t ----------------
// mup = mu at body t-1, muc = mu at body t (= rho*mup). po = ping-pong parity (old side).
__global__ void fused_k(const float* __restrict__ Y, const float* __restrict__ Wt,
                        float mup, float muc, int po) {
    int p = blockIdx.x * blockDim.x + threadIdx.x;
    if (p >= NPIX) return;
    int base = p & ~(IPIX - 1);
    int rem  = p & (IPIX - 1);
    int i = rem >> 7, j = rem & 127;
    int jw = (j + 127) & 127, je = (j + 1) & 127;
    int in_ = (i + 127) & 127, is = (i + 1) & 127;
    int pe = base + i * HW + je;     // east
    int ps = base + is * HW + j;     // south

    const float* __restrict__ G21o = d_G21[po];
    const float* __restrict__ G22o = d_G22[po];
    const float* __restrict__ Uho  = d_Uh[po];
    const float* __restrict__ Uvo  = d_Uv[po];
    float* __restrict__ G21n = d_G21[po ^ 1];
    float* __restrict__ G22n = d_G22[po ^ 1];
    float* __restrict__ Uhn  = d_Uh[po ^ 1];
    float* __restrict__ Uvn  = d_Uv[po ^ 1];

    float z  = d_Z[p];
    float zw = d_Z[base + i * HW + jw];
    float zn = d_Z[base + in_ * HW + j];
    float ze = d_Z[pe];
    float zs = d_Z[ps];

    float w  = Wt[p];
    float y  = Y[p];
    float g1 = d_G1[p];

    // ---- post of body t-1 (uses mup) ----
    float xn  = (w * y + mup * z - g1) / (w + mup);
    float g1n = g1 + mup * (xn - z);
    float dh  = z - zw;
    float dv  = z - zn;
    float g21 = G21o[p] + mup * (Uho[p] - dh);
    float g22 = G22o[p] + mup * (Uvo[p] - dv);

    // ---- pre of body t (uses muc) ----
    float thr  = LAM_C / muc;
    float inv2 = 1.0f / muc;
    float uh = shrinkf(dh - g21 * inv2, thr);
    float uv = shrinkf(dv - g22 * inv2, thr);

    // recompute east pixel's (G21', Uh') pointwise to form Bf(i,j+1)
    float dh_e  = ze - z;
    float g21e  = G21o[pe] + mup * (Uho[pe] - dh_e);
    float uh_e  = shrinkf(dh_e - g21e * inv2, thr);
    // recompute south pixel's (G22', Uv') for Cf(i+1,j)
    float dv_s  = zs - z;
    float g22s  = G22o[ps] + mup * (Uvo[ps] - dv_s);
    float uv_s  = shrinkf(dv_s - g22s * inv2, thr);

    float bf   = muc * uh   + g21;
    float bf_e = muc * uh_e + g21e;
    float cf   = muc * uv   + g22;
    float cf_s = muc * uv_s + g22s;

    d_G1[p]  = g1n;
    G21n[p]  = g21;
    G22n[p]  = g22;
    Uhn[p]   = uh;
    Uvn[p]   = uv;
    d_R[p] = muc * xn + g1n + (bf - bf_e) + (cf - cf_s);
}

// ---------------- solve: Z = H [ (H R H) ./ D ] H via 4 in-SMEM GEMMs ----------------
// GEMM convention: out[m][n] = sum_k A[k*PA + m] * B[k*PB + n]
// Thread (ty,tx) in 16x16; register tile strided: m = 16*ii+ty, n = 16*jj+tx (conflict-free LDS).
template <int PA, int PB>
__device__ __forceinline__ void mm128(const float* __restrict__ A,
                                      const float* __restrict__ B,
                                      float acc[8][8], int ty, int tx) {
#pragma unroll
    for (int ii = 0; ii < 8; ii++)
#pragma unroll
        for (int jj = 0; jj < 8; jj++) acc[ii][jj] = 0.f;
#pragma unroll 2
    for (int k = 0; k < 128; k++) {
        float a[8], b[8];
#pragma unroll
        for (int ii = 0; ii < 8; ii++) a[ii] = A[k * PA + ii * 16 + ty];
#pragma unroll
        for (int jj = 0; jj < 8; jj++) b[jj] = B[k * PB + jj * 16 + tx];
#pragma unroll
        for (int ii = 0; ii < 8; ii++)
#pragma unroll
            for (int jj = 0; jj < 8; jj++)
                acc[ii][jj] = fmaf(a[ii], b[jj], acc[ii][jj]);
    }
}

__global__ void __launch_bounds__(256, 1)
solve_k(float* __restrict__ outp, int toOut, float mu1, float mu2) {
    extern __shared__ float sm[];
    float* Hs   = sm;                    // 16384 floats (pitch 128)
    float* lamS = sm + IPIX;             // 128
    float* b0   = sm + IPIX + 128;       // 128*129
    float* b1   = b0 + HW * PITCHB;      // 128*129

    int tid = threadIdx.x;
    int ty = tid >> 4, tx = tid & 15;
    int base = blockIdx.x * IPIX;

    for (int k = tid; k < IPIX; k += 256) Hs[k] = d_Hmat[k];
    if (tid < HW) lamS[tid] = d_lam[tid];
    for (int k = tid; k < IPIX; k += 256) {
        int r = k >> 7, c = k & 127;
        b0[r * PITCHB + c] = d_R[base + k];
    }
    __syncthreads();

    float acc[8][8];

    // G1: T1[u][j] = sum_i H[i][u] * R[i][j]  -> store transposed b1[j][u]
    mm128<HW, PITCHB>(Hs, b0, acc, ty, tx);
#pragma unroll
    for (int ii = 0; ii < 8; ii++)
#pragma unroll
        for (int jj = 0; jj < 8; jj++)
            b1[(jj * 16 + tx) * PITCHB + (ii * 16 + ty)] = acc[ii][jj];
    __syncthreads();

    // G2: T2[u][v] = sum_j T1t[j][u] * H[j][v]; divide by denom -> b0[u][v]
    mm128<PITCHB, HW>(b1, Hs, acc, ty, tx);
    {
        float la[8];
#pragma unroll
        for (int ii = 0; ii < 8; ii++) la[ii] = lamS[ii * 16 + ty];
#pragma unroll
        for (int jj = 0; jj < 8; jj++) {
            float lb = lamS[jj * 16 + tx];
#pragma unroll
            for (int ii = 0; ii < 8; ii++) {
                float den = mu1 + mu2 * (la[ii] + lb);
                b0[(ii * 16 + ty) * PITCHB + (jj * 16 + tx)] = acc[ii][jj] / den;
            }
        }
    }
    __syncthreads();

    // G3: T3[i][v] = sum_u H[u][i] * Zh[u][v] -> store transposed b1[v][i]
    mm128<HW, PITCHB>(Hs, b0, acc, ty, tx);
#pragma unroll
    for (int ii = 0; ii < 8; ii++)
#pragma unroll
        for (int jj = 0; jj < 8; jj++)
            b1[(jj * 16 + tx) * PITCHB + (ii * 16 + ty)] = acc[ii][jj];
    __syncthreads();

    // G4: Z[i][j] = sum_v T3t[v][i] * H[v][j] -> global
    mm128<PITCHB, HW>(b1, Hs, acc, ty, tx);
    float* dst = toOut ? outp : d_Z;
#pragma unroll
    for (int ii = 0; ii < 8; ii++)
#pragma unroll
        for (int jj = 0; jj < 8; jj++)
            dst[base + (ii * 16 + ty) * HW + (jj * 16 + tx)] = acc[ii][jj];
}

// ---------------- launcher ----------------
extern "C" void kernel_launch(void* const* d_in, const int* in_sizes, int n_in,
                              void* d_out, int out_size) {
    const float* Y  = (const float*)d_in[0];
    const float* Wt = (const float*)d_in[1];
    float* outp = (float*)d_out;
    (void)in_sizes; (void)n_in; (void)out_size;

    const size_t shbytes = (size_t)(IPIX + 128 + 2 * HW * PITCHB) * sizeof(float); // 198144
    cudaFuncSetAttribute(solve_k, cudaFuncAttributeMaxDynamicSharedMemorySize, (int)shbytes);

    const int EB = 256;
    const int EG = NPIX / EB;   // 7936

    init_k<<<EG, EB>>>();

    float mu = 0.1f;            // MU1 == MU2 at every step (same init, same rho)
    pre0_k<<<EG, EB>>>(Y, mu);
    solve_k<<<NIMG, 256, shbytes>>>(outp, 0, mu, mu);

    for (int t = 1; t < ITERS; t++) {
        float mup = mu;
        mu = mu * 1.05f;        // matches reference fp32 mu update
        fused_k<<<EG, EB>>>(Y, Wt, mup, mu, (t - 1) & 1);
        solve_k<<<NIMG, 256, shbytes>>>(outp, (t == ITERS - 1) ? 1 : 0, mu, mu);
    }
}

// round 10
// speedup vs baseline: 1.2358x; 1.2349x over previous
#include <cuda_runtime.h>
#include <math.h>

// Problem constants: shape (4, 31, 128, 128) fp32
#define HW      128
#define IPIX    (HW * HW)          // 16384
#define NIMG    124                // 4*31
#define NPIX    (NIMG * IPIX)      // 2031616
#define PITCH   132                // padded pitch (mult of 4 -> 16B-aligned rows)
#define LAM_C   0.1f
#define ITERS   20

typedef unsigned long long u64;

// ---------------- persistent device state (no allocations allowed) ----------------
__device__ float d_Z[NPIX];
__device__ float d_R[NPIX];
__device__ float d_G1[NPIX];
__device__ float d_G21[2][NPIX];
__device__ float d_G22[2][NPIX];
__device__ float d_Uh[2][NPIX];
__device__ float d_Uv[2][NPIX];
__device__ float d_Hmat[IPIX];     // Hartley matrix (symmetric, orthogonal, H^2 = I)
__device__ float d_lam[HW];        // eigenvalues of 1D circulant D^T D: 2 - 2cos(2*pi*k/128)

__device__ __forceinline__ float shrinkf(float x, float t) {
    float m = fabsf(x) - t;
    m = m > 0.f ? m : 0.f;
    return copysignf(m, x);
}

// ---- packed fp32x2 helpers (Blackwell FFMA2: 2x fp32 FMA per issue slot) ----
__device__ __forceinline__ u64 pk2(float lo, float hi) {
    u64 r; asm("mov.b64 %0,{%1,%2};" : "=l"(r) : "f"(lo), "f"(hi)); return r;
}
__device__ __forceinline__ void upk2(u64 v, float& lo, float& hi) {
    asm("mov.b64 {%0,%1},%2;" : "=f"(lo), "=f"(hi) : "l"(v));
}
__device__ __forceinline__ u64 ffma2(u64 a, u64 b, u64 c) {
    u64 d; asm("fma.rn.f32x2 %0,%1,%2,%3;" : "=l"(d) : "l"(a), "l"(b), "l"(c)); return d;
}

// ---------------- init: build H, lambda, zero dual state ----------------
__global__ void init_k() {
    int idx = blockIdx.x * blockDim.x + threadIdx.x;
    if (idx < NPIX) {
        d_G1[idx] = 0.f;
        d_G21[0][idx] = 0.f;
        d_G22[0][idx] = 0.f;
    }
    if (idx < IPIX) {
        int a = idx >> 7, b = idx & 127;
        int t = (a * b) & 127;                        // cas is 2*pi periodic
        double ang = (double)t * 0.04908738521234052; // 2*pi/128
        double s = sin(ang), c = cos(ang);
        d_Hmat[idx] = (float)((s + c) * 0.08838834764831845); // 1/sqrt(128)
    }
    if (idx < HW) {
        double ang = (double)idx * 0.04908738521234052;
        d_lam[idx] = (float)(2.0 - 2.0 * cos(ang));
    }
}

// ---------------- pre of iteration 0 (state: Z=X=Y, G=0) ----------------
__global__ void pre0_k(const float* __restrict__ Y, float mu) {
    int p = blockIdx.x * blockDim.x + threadIdx.x;
    if (p >= NPIX) return;
    int base = p & ~(IPIX - 1);
    int rem  = p & (IPIX - 1);
    int i = rem >> 7, j = rem & 127;
    int jw = (j + 127) & 127, je = (j + 1) & 127;
    int in_ = (i + 127) & 127, is = (i + 1) & 127;

    float y  = Y[p];
    float yw = Y[base + i * HW + jw];
    float yn = Y[base + in_ * HW + j];
    float ye = Y[base + i * HW + je];
    float ys = Y[base + is * HW + j];

    float thr = LAM_C / mu;
    float uh   = shrinkf(y - yw, thr);
    float uv   = shrinkf(y - yn, thr);
    float uh_e = shrinkf(ye - y, thr);
    float uv_s = shrinkf(ys - y, thr);

    d_Uh[0][p] = uh;
    d_Uv[0][p] = uv;
    d_R[p] = mu * y + mu * ((uh - uh_e) + (uv - uv_s));
}

// ---------------- fused (float4): post of body t-1 + pre of body t ----------------
// One thread handles 4 consecutive j. mup = mu at body t-1, muc = rho*mup.
__global__ void fused4_k(const float* __restrict__ Y, const float* __restrict__ Wt,
                         float mup, float muc, int po) {
    int q = blockIdx.x * blockDim.x + threadIdx.x;
    if (q >= NPIX / 4) return;
    int img  = q >> 12;             // 4096 quads per image
    int rem  = q & 4095;
    int i    = rem >> 5;
    int j0   = (rem & 31) * 4;
    int base = img << 14;
    int rowp = base + i * HW;
    int p    = rowp + j0;
    int in_  = (i + 127) & 127, is = (i + 1) & 127;
    int pn   = base + in_ * HW + j0;
    int ps   = base + is * HW + j0;
    int je   = (j0 + 4) & 127;      // column of east neighbor of z[3]
    int jw   = (j0 + 127) & 127;

    const float* __restrict__ G21o = d_G21[po];
    const float* __restrict__ G22o = d_G22[po];
    const float* __restrict__ Uho  = d_Uh[po];
    const float* __restrict__ Uvo  = d_Uv[po];
    float* __restrict__ G21n = d_G21[po ^ 1];
    float* __restrict__ G22n = d_G22[po ^ 1];
    float* __restrict__ Uhn  = d_Uh[po ^ 1];
    float* __restrict__ Uvn  = d_Uv[po ^ 1];

    float4 zc4  = *(const float4*)&d_Z[p];
    float4 zn4  = *(const float4*)&d_Z[pn];
    float4 zs4  = *(const float4*)&d_Z[ps];
    float  zw   = d_Z[rowp + jw];
    float  ze   = d_Z[rowp + je];
    float4 w4   = *(const float4*)&Wt[p];
    float4 y4   = *(const float4*)&Y[p];
    float4 g14  = *(const float4*)&d_G1[p];
    float4 g21c = *(const float4*)&G21o[p];
    float4 uhc  = *(const float4*)&Uho[p];
    float4 g22c = *(const float4*)&G22o[p];
    float4 uvc  = *(const float4*)&Uvo[p];
    float4 g22s4 = *(const float4*)&G22o[ps];
    float4 uvs4  = *(const float4*)&Uvo[ps];
    float  g21e_o = G21o[rowp + je];
    float  uhe_o  = Uho[rowp + je];

    float z[4]  = {zc4.x, zc4.y, zc4.z, zc4.w};
    float zn[4] = {zn4.x, zn4.y, zn4.z, zn4.w};
    float zs[4] = {zs4.x, zs4.y, zs4.z, zs4.w};
    float w[4]  = {w4.x, w4.y, w4.z, w4.w};
    float y[4]  = {y4.x, y4.y, y4.z, y4.w};
    float g1[4] = {g14.x, g14.y, g14.z, g14.w};
    float g21ca[4] = {g21c.x, g21c.y, g21c.z, g21c.w};
    float uhca[4]  = {uhc.x, uhc.y, uhc.z, uhc.w};
    float g22ca[4] = {g22c.x, g22c.y, g22c.z, g22c.w};
    float uvca[4]  = {uvc.x, uvc.y, uvc.z, uvc.w};
    float g22sa[4] = {g22s4.x, g22s4.y, g22s4.z, g22s4.w};
    float uvsa[4]  = {uvs4.x, uvs4.y, uvs4.z, uvs4.w};

    float thr  = LAM_C / muc;
    float inv2 = 1.0f / muc;

    // horizontal chain t=0..4 (index 4 is the east pixel's own values)
    float dh[5], g21[5], uh[5], bf[5];
#pragma unroll
    for (int t = 0; t < 4; t++) dh[t] = z[t] - (t == 0 ? zw : z[t - 1]);
    dh[4] = ze - z[3];
#pragma unroll
    for (int t = 0; t < 4; t++) g21[t] = g21ca[t] + mup * (uhca[t] - dh[t]);
    g21[4] = g21e_o + mup * (uhe_o - dh[4]);
#pragma unroll
    for (int t = 0; t < 5; t++) {
        uh[t] = shrinkf(dh[t] - g21[t] * inv2, thr);
        bf[t] = muc * uh[t] + g21[t];
    }

    float4 outG1, outG21, outG22, outUh, outUv, outR;
    float* pG1  = (float*)&outG1;
    float* pG21 = (float*)&outG21;
    float* pG22 = (float*)&outG22;
    float* pUh  = (float*)&outUh;
    float* pUv  = (float*)&outUv;
    float* pR   = (float*)&outR;

#pragma unroll
    for (int t = 0; t < 4; t++) {
        float dv   = z[t] - zn[t];
        float dv_s = zs[t] - z[t];
        float g22  = g22ca[t] + mup * (uvca[t] - dv);
        float g22s = g22sa[t] + mup * (uvsa[t] - dv_s);
        float uv   = shrinkf(dv - g22 * inv2, thr);
        float uv_s = shrinkf(dv_s - g22s * inv2, thr);
        float cf   = muc * uv + g22;
        float cf_s = muc * uv_s + g22s;

        float xn  = (w[t] * y[t] + mup * z[t] - g1[t]) / (w[t] + mup);
        float g1n = g1[t] + mup * (xn - z[t]);

        pG1[t]  = g1n;
        pG21[t] = g21[t];
        pG22[t] = g22;
        pUh[t]  = uh[t];
        pUv[t]  = uv;
        pR[t]   = muc * xn + g1n + (bf[t] - bf[t + 1]) + (cf - cf_s);
    }

    *(float4*)&d_G1[p] = outG1;
    *(float4*)&G21n[p] = outG21;
    *(float4*)&G22n[p] = outG22;
    *(float4*)&Uhn[p]  = outUh;
    *(float4*)&Uvn[p]  = outUv;
    *(float4*)&d_R[p]  = outR;
}

// ---------------- packed GEMM: out[m][n] = sum_k A[m][k] * B[k][n] ----------------
// A row-major [m][k] pitch PA (H is symmetric, so H works as A directly).
// B row-major [k][n] pitch PB. Thread (ty,tx): m = 16*ii+ty, n = tx*8+jj.
// Accumulators packed 2-wide along n (FFMA2). A loads: LDS.128 across k
// (2-address broadcast per instr). B loads: 2x LDS.128 per k, conflict-light.
template <int PA, int PB>
__device__ __forceinline__ void mmv(const float* __restrict__ A,
                                    const float* __restrict__ B,
                                    u64 acc[8][4], int ty, int tx) {
#pragma unroll
    for (int ii = 0; ii < 8; ii++)
#pragma unroll
        for (int qq = 0; qq < 4; qq++) acc[ii][qq] = 0ull;   // two packed +0.0f

    for (int k0 = 0; k0 < 128; k0 += 4) {
        float4 a4[8];
#pragma unroll
        for (int ii = 0; ii < 8; ii++)
            a4[ii] = *(const float4*)(A + (ii * 16 + ty) * PA + k0);
        const float* af = (const float*)a4;
#pragma unroll
        for (int s = 0; s < 4; s++) {
            const float* Br = B + (k0 + s) * PB + tx * 8;
            float4 u = *(const float4*)Br;
            float4 v = *(const float4*)(Br + 4);
            u64 b2[4];
            b2[0] = pk2(u.x, u.y); b2[1] = pk2(u.z, u.w);
            b2[2] = pk2(v.x, v.y); b2[3] = pk2(v.z, v.w);
#pragma unroll
            for (int ii = 0; ii < 8; ii++) {
                float as = af[ii * 4 + s];
                u64 a2 = pk2(as, as);
#pragma unroll
                for (int qq = 0; qq < 4; qq++)
                    acc[ii][qq] = ffma2(a2, b2[qq], acc[ii][qq]);
            }
        }
    }
}

// ---------------- solve: Z = H [ (H R H) ./ D ] H via 4 in-SMEM GEMMs ----------------
__global__ void __launch_bounds__(256, 1)
solve_k(float* __restrict__ outp, int toOut, float mu1, float mu2) {
    extern __shared__ float sm[];
    float* Hs   = sm;                    // 16384 floats (pitch 128)
    float* lamS = sm + IPIX;             // 128
    float* b0   = sm + IPIX + 128;       // 128 * PITCH
    float* b1   = b0 + HW * PITCH;       // 128 * PITCH

    int tid = threadIdx.x;
    int ty = tid >> 4, tx = tid & 15;
    int base = blockIdx.x * IPIX;

    {
        const float4* Hg = (const float4*)d_Hmat;
        float4* Hd = (float4*)Hs;
        for (int k = tid; k < IPIX / 4; k += 256) Hd[k] = Hg[k];
        if (tid < HW) lamS[tid] = d_lam[tid];
        const float4* Rg = (const float4*)(d_R + base);
        for (int k = tid; k < IPIX / 4; k += 256) {
            int r = k >> 5, c = k & 31;
            *(float4*)&b0[r * PITCH + c * 4] = Rg[k];
        }
    }
    __syncthreads();

    u64 acc[8][4];

    // Stage 1: T1[u][j] = sum_i H[i][u] R[i][j]  (H symmetric -> A=H) -> b1 row-major
    mmv<HW, PITCH>(Hs, b0, acc, ty, tx);
#pragma unroll
    for (int ii = 0; ii < 8; ii++) {
        float* row = b1 + (ii * 16 + ty) * PITCH + tx * 8;
#pragma unroll
        for (int qq = 0; qq < 4; qq++)
            *(u64*)(row + 2 * qq) = acc[ii][qq];
    }
    __syncthreads();

    // Stage 2: T2[u][v] = sum_j T1[u][j] H[j][v]; divide by denom -> b0 row-major
    mmv<PITCH, HW>(b1, Hs, acc, ty, tx);
#pragma unroll
    for (int ii = 0; ii < 8; ii++) {
        float la = lamS[ii * 16 + ty];
        float* row = b0 + (ii * 16 + ty) * PITCH + tx * 8;
#pragma unroll
        for (int qq = 0; qq < 4; qq++) {
            float f0, f1;
            upk2(acc[ii][qq], f0, f1);
            int n0 = tx * 8 + 2 * qq;
            float d0 = mu1 + mu2 * (la + lamS[n0]);
            float d1 = mu1 + mu2 * (la + lamS[n0 + 1]);
            *(u64*)(row + 2 * qq) = pk2(f0 / d0, f1 / d1);
        }
    }
    __syncthreads();

    // Stage 3: T3[i][v] = sum_u H[u][i] Zh[u][v] -> b1 row-major
    mmv<HW, PITCH>(Hs, b0, acc, ty, tx);
#pragma unroll
    for (int ii = 0; ii < 8; ii++) {
        float* row = b1 + (ii * 16 + ty) * PITCH + tx * 8;
#pragma unroll
        for (int qq = 0; qq < 4; qq++)
            *(u64*)(row + 2 * qq) = acc[ii][qq];
    }
    __syncthreads();

    // Stage 4: Z[i][j] = sum_v T3[i][v] H[v][j] -> global
    mmv<PITCH, HW>(b1, Hs, acc, ty, tx);
    float* dst = toOut ? outp : d_Z;
#pragma unroll
    for (int ii = 0; ii < 8; ii++) {
        float* row = dst + base + (ii * 16 + ty) * HW + tx * 8;
#pragma unroll
        for (int qq = 0; qq < 4; qq++)
            *(u64*)(row + 2 * qq) = acc[ii][qq];
    }
}

// ---------------- launcher ----------------
extern "C" void kernel_launch(void* const* d_in, const int* in_sizes, int n_in,
                              void* d_out, int out_size) {
    const float* Y  = (const float*)d_in[0];
    const float* Wt = (const float*)d_in[1];
    float* outp = (float*)d_out;
    (void)in_sizes; (void)n_in; (void)out_size;

    const size_t shbytes = (size_t)(IPIX + 128 + 2 * HW * PITCH) * sizeof(float); // 201216
    cudaFuncSetAttribute(solve_k, cudaFuncAttributeMaxDynamicSharedMemorySize, (int)shbytes);

    const int EB = 256;
    const int EG  = NPIX / EB;        // 7936 (scalar kernels)
    const int EG4 = (NPIX / 4) / EB;  // 1984 (float4 fused kernel)

    init_k<<<EG, EB>>>();

    float mu = 0.1f;                  // MU1 == MU2 at every step (same init, same rho)
    pre0_k<<<EG, EB>>>(Y, mu);
    solve_k<<<NIMG, 256, shbytes>>>(outp, 0, mu, mu);

    for (int t = 1; t < ITERS; t++) {
        float mup = mu;
        mu = mu * 1.05f;              // matches reference fp32 mu update
        fused4_k<<<EG4, EB>>>(Y, Wt, mup, mu, (t - 1) & 1);
        solve_k<<<NIMG, 256, shbytes>>>(outp, (t == ITERS - 1) ? 1 : 0, mu, mu);
    }
}

// round 12
// speedup vs baseline: 2.3226x; 1.8794x over previous
#include <cuda_runtime.h>
#include <cuda_bf16.h>
#include <math.h>

// Problem constants: shape (4, 31, 128, 128) fp32
#define HW      128
#define IPIX    (HW * HW)          // 16384
#define NIMG    124                // 4*31
#define NPIX    (NIMG * IPIX)      // 2031616
#define LAM_C   0.1f
#define ITERS   20
#define PB      136                // SMEM tile pitch in bf16 elements (272 B rows)
#define PBB     272                // pitch bytes
#define TILE    (HW * PBB)         // 34816 bytes per bf16 tile

typedef unsigned long long u64;
typedef unsigned int u32;

// ---------------- persistent device state (no allocations allowed) ----------------
__device__ float d_Z[NPIX];
__device__ float d_R[NPIX];
__device__ float d_G1[NPIX];
__device__ float d_G21[2][NPIX];
__device__ float d_G22[2][NPIX];
__device__ float d_Uh[2][NPIX];
__device__ float d_Uv[2][NPIX];
__device__ float d_lam[HW];              // 2 - 2cos(2*pi*k/128)
__device__ __nv_bfloat16 d_Hh[IPIX];     // Hartley matrix hi-bf16, row-major
__device__ __nv_bfloat16 d_Hl[IPIX];     // lo residual, row-major

__device__ __forceinline__ float shrinkf(float x, float t) {
    float m = fabsf(x) - t;
    m = m > 0.f ? m : 0.f;
    return copysignf(m, x);
}

// ---------------- init: build H hi/lo bf16, lambda, zero dual state ----------------
__global__ void init_k() {
    int idx = blockIdx.x * blockDim.x + threadIdx.x;
    if (idx < NPIX) {
        d_G1[idx] = 0.f;
        d_G21[0][idx] = 0.f;
        d_G22[0][idx] = 0.f;
    }
    if (idx < IPIX) {
        int a = idx >> 7, b = idx & 127;
        int t = (a * b) & 127;                        // cas is 2*pi periodic
        double ang = (double)t * 0.04908738521234052; // 2*pi/128
        double s = sin(ang), c = cos(ang);
        float v = (float)((s + c) * 0.08838834764831845); // 1/sqrt(128)
        __nv_bfloat16 h = __float2bfloat16(v);
        __nv_bfloat16 l = __float2bfloat16(v - __bfloat162float(h));
        d_Hh[idx] = h;
        d_Hl[idx] = l;
    }
    if (idx < HW) {
        double ang = (double)idx * 0.04908738521234052;
        d_lam[idx] = (float)(2.0 - 2.0 * cos(ang));
    }
}

// ---------------- pre of iteration 0 (state: Z=X=Y, G=0) ----------------
__global__ void pre0_k(const float* __restrict__ Y, float mu) {
    int p = blockIdx.x * blockDim.x + threadIdx.x;
    if (p >= NPIX) return;
    int base = p & ~(IPIX - 1);
    int rem  = p & (IPIX - 1);
    int i = rem >> 7, j = rem & 127;
    int jw = (j + 127) & 127, je = (j + 1) & 127;
    int in_ = (i + 127) & 127, is = (i + 1) & 127;

    float y  = Y[p];
    float yw = Y[base + i * HW + jw];
    float yn = Y[base + in_ * HW + j];
    float ye = Y[base + i * HW + je];
    float ys = Y[base + is * HW + j];

    float thr = LAM_C / mu;
    float uh   = shrinkf(y - yw, thr);
    float uv   = shrinkf(y - yn, thr);
    float uh_e = shrinkf(ye - y, thr);
    float uv_s = shrinkf(ys - y, thr);

    d_Uh[0][p] = uh;
    d_Uv[0][p] = uv;
    d_R[p] = mu * y + mu * ((uh - uh_e) + (uv - uv_s));
}

// ---------------- fused (float4): post of body t-1 + pre of body t ----------------
__global__ void fused4_k(const float* __restrict__ Y, const float* __restrict__ Wt,
                         float mup, float muc, int po) {
    int q = blockIdx.x * blockDim.x + threadIdx.x;
    if (q >= NPIX / 4) return;
    int img  = q >> 12;
    int rem  = q & 4095;
    int i    = rem >> 5;
    int j0   = (rem & 31) * 4;
    int base = img << 14;
    int rowp = base + i * HW;
    int p    = rowp + j0;
    int in_  = (i + 127) & 127, is = (i + 1) & 127;
    int pn   = base + in_ * HW + j0;
    int ps   = base + is * HW + j0;
    int je   = (j0 + 4) & 127;
    int jw   = (j0 + 127) & 127;

    const float* __restrict__ G21o = d_G21[po];
    const float* __restrict__ G22o = d_G22[po];
    const float* __restrict__ Uho  = d_Uh[po];
    const float* __restrict__ Uvo  = d_Uv[po];
    float* __restrict__ G21n = d_G21[po ^ 1];
    float* __restrict__ G22n = d_G22[po ^ 1];
    float* __restrict__ Uhn  = d_Uh[po ^ 1];
    float* __restrict__ Uvn  = d_Uv[po ^ 1];

    float4 zc4  = *(const float4*)&d_Z[p];
    float4 zn4  = *(const float4*)&d_Z[pn];
    float4 zs4  = *(const float4*)&d_Z[ps];
    float  zw   = d_Z[rowp + jw];
    float  ze   = d_Z[rowp + je];
    float4 w4   = *(const float4*)&Wt[p];
    float4 y4   = *(const float4*)&Y[p];
    float4 g14  = *(const float4*)&d_G1[p];
    float4 g21c = *(const float4*)&G21o[p];
    float4 uhc  = *(const float4*)&Uho[p];
    float4 g22c = *(const float4*)&G22o[p];
    float4 uvc  = *(const float4*)&Uvo[p];
    float4 g22s4 = *(const float4*)&G22o[ps];
    float4 uvs4  = *(const float4*)&Uvo[ps];
    float  g21e_o = G21o[rowp + je];
    float  uhe_o  = Uho[rowp + je];

    float z[4]  = {zc4.x, zc4.y, zc4.z, zc4.w};
    float zn[4] = {zn4.x, zn4.y, zn4.z, zn4.w};
    float zs[4] = {zs4.x, zs4.y, zs4.z, zs4.w};
    float w[4]  = {w4.x, w4.y, w4.z, w4.w};
    float y[4]  = {y4.x, y4.y, y4.z, y4.w};
    float g1[4] = {g14.x, g14.y, g14.z, g14.w};
    float g21ca[4] = {g21c.x, g21c.y, g21c.z, g21c.w};
    float uhca[4]  = {uhc.x, uhc.y, uhc.z, uhc.w};
    float g22ca[4] = {g22c.x, g22c.y, g22c.z, g22c.w};
    float uvca[4]  = {uvc.x, uvc.y, uvc.z, uvc.w};
    float g22sa[4] = {g22s4.x, g22s4.y, g22s4.z, g22s4.w};
    float uvsa[4]  = {uvs4.x, uvs4.y, uvs4.z, uvs4.w};

    float thr  = LAM_C / muc;
    float inv2 = 1.0f / muc;

    float dh[5], g21[5], uh[5], bf[5];
#pragma unroll
    for (int t = 0; t < 4; t++) dh[t] = z[t] - (t == 0 ? zw : z[t - 1]);
    dh[4] = ze - z[3];
#pragma unroll
    for (int t = 0; t < 4; t++) g21[t] = g21ca[t] + mup * (uhca[t] - dh[t]);
    g21[4] = g21e_o + mup * (uhe_o - dh[4]);
#pragma unroll
    for (int t = 0; t < 5; t++) {
        uh[t] = shrinkf(dh[t] - g21[t] * inv2, thr);
        bf[t] = muc * uh[t] + g21[t];
    }

    float4 outG1, outG21, outG22, outUh, outUv, outR;
    float* pG1  = (float*)&outG1;
    float* pG21 = (float*)&outG21;
    float* pG22 = (float*)&outG22;
    float* pUh  = (float*)&outUh;
    float* pUv  = (float*)&outUv;
    float* pR   = (float*)&outR;

#pragma unroll
    for (int t = 0; t < 4; t++) {
        float dv   = z[t] - zn[t];
        float dv_s = zs[t] - z[t];
        float g22  = g22ca[t] + mup * (uvca[t] - dv);
        float g22s = g22sa[t] + mup * (uvsa[t] - dv_s);
        float uv   = shrinkf(dv - g22 * inv2, thr);
        float uv_s = shrinkf(dv_s - g22s * inv2, thr);
        float cf   = muc * uv + g22;
        float cf_s = muc * uv_s + g22s;

        float xn  = (w[t] * y[t] + mup * z[t] - g1[t]) / (w[t] + mup);
        float g1n = g1[t] + mup * (xn - z[t]);

        pG1[t]  = g1n;
        pG21[t] = g21[t];
        pG22[t] = g22;
        pUh[t]  = uh[t];
        pUv[t]  = uv;
        pR[t]   = muc * xn + g1n + (bf[t] - bf[t + 1]) + (cf - cf_s);
    }

    *(float4*)&d_G1[p] = outG1;
    *(float4*)&G21n[p] = outG21;
    *(float4*)&G22n[p] = outG22;
    *(float4*)&Uhn[p]  = outUh;
    *(float4*)&Uvn[p]  = outUv;
    *(float4*)&d_R[p]  = outR;
}

// ================= mma.sync bf16-split solve =================

__device__ __forceinline__ u32 smem_u32(const void* p) {
    u32 a;
    asm("{ .reg .u64 t; cvta.to.shared.u64 t, %1; cvt.u32.u64 %0, t; }" : "=r"(a) : "l"(p));
    return a;
}

__device__ __forceinline__ void ldm4(u32 addr, u32 r[4]) {
    asm volatile("ldmatrix.sync.aligned.m8n8.x4.shared.b16 {%0,%1,%2,%3}, [%4];"
        : "=r"(r[0]), "=r"(r[1]), "=r"(r[2]), "=r"(r[3]) : "r"(addr));
}

__device__ __forceinline__ void mma_bf16(float acc[4], const u32 a[4], u32 b0, u32 b1) {
    asm volatile("mma.sync.aligned.m16n8k16.row.col.f32.bf16.bf16.f32 "
        "{%0,%1,%2,%3}, {%4,%5,%6,%7}, {%8,%9}, {%0,%1,%2,%3};"
        : "+f"(acc[0]), "+f"(acc[1]), "+f"(acc[2]), "+f"(acc[3])
        : "r"(a[0]), "r"(a[1]), "r"(a[2]), "r"(a[3]), "r"(b0), "r"(b1));
}

// split two fp32 into packed bf16 hi + packed bf16 lo (elem0 in low half)
__device__ __forceinline__ void split2(float c0, float c1, u32& hi, u32& lo) {
    asm("cvt.rn.bf16x2.f32 %0, %1, %2;" : "=r"(hi) : "f"(c1), "f"(c0));
    float f0 = __uint_as_float(hi << 16);
    float f1 = __uint_as_float(hi & 0xFFFF0000u);
    float l0 = c0 - f0, l1 = c1 - f1;
    asm("cvt.rn.bf16x2.f32 %0, %1, %2;" : "=r"(lo) : "f"(l1), "f"(l0));
}

// One NT stage: acc[16][4] = (Hh+Hl) * (Bh+Bl)^T  (3-term split, fp32 accum).
// A = H rows [wid*16, wid*16+16); full N=128. All operands row-major pitch PBB.
__device__ __forceinline__ void gemm_stage(u32 Hh_a, u32 Hl_a, u32 Bh_a, u32 Bl_a,
                                           float acc[16][4], int lane, int wid) {
#pragma unroll
    for (int i = 0; i < 16; i++)
#pragma unroll
        for (int j = 0; j < 4; j++) acc[i][j] = 0.f;

    int q = lane >> 3, r = lane & 7;
    u32 aoff = (u32)((wid * 16 + (q & 1) * 8 + r) * PBB + (q >> 1) * 16);
    u32 boff = (u32)(((q >> 1) * 8 + r) * PBB + (q & 1) * 16);

#pragma unroll 1
    for (int ks = 0; ks < 8; ks++) {
        u32 ah[4], al[4];
        ldm4(Hh_a + aoff + ks * 32, ah);
        ldm4(Hl_a + aoff + ks * 32, al);
#pragma unroll
        for (int jt = 0; jt < 8; jt++) {
            u32 bh[4], bl[4];
            u32 ba = boff + (u32)(jt * 16 * PBB) + ks * 32;
            ldm4(Bh_a + ba, bh);
            ldm4(Bl_a + ba, bl);
            mma_bf16(acc[2 * jt],     ah, bh[0], bh[1]);
            mma_bf16(acc[2 * jt + 1], ah, bh[2], bh[3]);
            mma_bf16(acc[2 * jt],     ah, bl[0], bl[1]);
            mma_bf16(acc[2 * jt + 1], ah, bl[2], bl[3]);
            mma_bf16(acc[2 * jt],     al, bh[0], bh[1]);
            mma_bf16(acc[2 * jt + 1], al, bh[2], bh[3]);
        }
    }
}

// store acc as hi/lo bf16 tiles, row-major pitch PBB (conflict-free per nt)
__device__ __forceinline__ void store_tile(char* dh, char* dl, float acc[16][4],
                                           int lane, int wid) {
    int g = lane >> 2, t = lane & 3;
    int row0 = wid * 16 + g;
#pragma unroll
    for (int nt = 0; nt < 16; nt++) {
        int colb = (nt * 8 + t * 2) * 2;
        u32 hi, lo;
        split2(acc[nt][0], acc[nt][1], hi, lo);
        *(u32*)(dh + row0 * PBB + colb) = hi;
        *(u32*)(dl + row0 * PBB + colb) = lo;
        split2(acc[nt][2], acc[nt][3], hi, lo);
        *(u32*)(dh + (row0 + 8) * PBB + colb) = hi;
        *(u32*)(dl + (row0 + 8) * PBB + colb) = lo;
    }
}

// SMEM: lam 512B, then 6 tiles: Hh, Hl, B0h, B0l, B1h, B1l. Total 209408 B.
#define SM_TOTAL (512 + 6 * TILE)

__global__ void __launch_bounds__(256, 1)
solve_k(float* __restrict__ outp, int toOut, float mu1, float mu2) {
    extern __shared__ char smc[];
    float* lamS = (float*)smc;
    char* Hh  = smc + 512;
    char* Hl  = Hh + TILE;
    char* B0h = Hl + TILE;
    char* B0l = B0h + TILE;
    char* B1h = B0l + TILE;
    char* B1l = B1h + TILE;

    int tid = threadIdx.x;
    int wid = tid >> 5, lane = tid & 31;
    int base = blockIdx.x * IPIX;

    // copy H hi/lo into pitched SMEM tiles (int4: 16 per row of 256B)
    {
        const int4* sh = (const int4*)d_Hh;
        const int4* sl = (const int4*)d_Hl;
        for (int i = tid; i < 2048; i += 256) {
            int row = i >> 4, w = i & 15;
            *(int4*)(Hh + row * PBB + w * 16) = sh[i];
            *(int4*)(Hl + row * PBB + w * 16) = sl[i];
        }
    }
    if (tid < HW) lamS[tid] = d_lam[tid];

    // convert R (fp32) -> B0 hi/lo bf16 tiles
    {
        const float2* Rg = (const float2*)(d_R + base);
#pragma unroll 4
        for (int e = 0; e < 32; e++) {
            int idx = e * 256 + tid;      // float2 index, 8192 total
            float2 v = Rg[idx];
            int r = idx >> 6, c = (idx & 63) * 2;
            u32 hi, lo;
            split2(v.x, v.y, hi, lo);
            *(u32*)(B0h + r * PBB + c * 2) = hi;
            *(u32*)(B0l + r * PBB + c * 2) = lo;
        }
    }
    __syncthreads();

    u32 Hh_a = smem_u32(Hh), Hl_a = smem_u32(Hl);
    u32 B0h_a = smem_u32(B0h), B0l_a = smem_u32(B0l);
    u32 B1h_a = smem_u32(B1h), B1l_a = smem_u32(B1l);

    float acc[16][4];
    int g = lane >> 2, t = lane & 3;
    int row0 = wid * 16 + g;

    // Stage 1: M1 = H * R^T -> B1
    gemm_stage(Hh_a, Hl_a, B0h_a, B0l_a, acc, lane, wid);
    store_tile(B1h, B1l, acc, lane, wid);
    __syncthreads();

    // Stage 2: M2 = H * M1^T = (H R H)^T; divide by symmetric denom -> B0
    gemm_stage(Hh_a, Hl_a, B1h_a, B1l_a, acc, lane, wid);
    {
        float la0 = lamS[row0], la1 = lamS[row0 + 8];
#pragma unroll
        for (int nt = 0; nt < 16; nt++) {
            int col = nt * 8 + t * 2;
            float lb0 = lamS[col], lb1 = lamS[col + 1];
            acc[nt][0] = __fdividef(acc[nt][0], mu1 + mu2 * (la0 + lb0));
            acc[nt][1] = __fdividef(acc[nt][1], mu1 + mu2 * (la0 + lb1));
            acc[nt][2] = __fdividef(acc[nt][2], mu1 + mu2 * (la1 + lb0));
            acc[nt][3] = __fdividef(acc[nt][3], mu1 + mu2 * (la1 + lb1));
        }
    }
    store_tile(B0h, B0l, acc, lane, wid);
    __syncthreads();

    // Stage 3: M3 = H * W^T -> B1
    gemm_stage(Hh_a, Hl_a, B0h_a, B0l_a, acc, lane, wid);
    store_tile(B1h, B1l, acc, lane, wid);
    __syncthreads();

    // Stage 4: Z = H * M3^T -> global (row-major, exact orientation)
    gemm_stage(Hh_a, Hl_a, B1h_a, B1l_a, acc, lane, wid);
    {
        float* dst = (toOut ? outp : d_Z) + base;
#pragma unroll
        for (int nt = 0; nt < 16; nt++) {
            int col = nt * 8 + t * 2;
            *(float2*)&dst[row0 * HW + col]       = make_float2(acc[nt][0], acc[nt][1]);
            *(float2*)&dst[(row0 + 8) * HW + col] = make_float2(acc[nt][2], acc[nt][3]);
        }
    }
}

// ---------------- launcher ----------------
extern "C" void kernel_launch(void* const* d_in, const int* in_sizes, int n_in,
                              void* d_out, int out_size) {
    const float* Y  = (const float*)d_in[0];
    const float* Wt = (const float*)d_in[1];
    float* outp = (float*)d_out;
    (void)in_sizes; (void)n_in; (void)out_size;

    cudaFuncSetAttribute(solve_k, cudaFuncAttributeMaxDynamicSharedMemorySize, SM_TOTAL);

    const int EB = 256;
    const int EG  = NPIX / EB;        // 7936
    const int EG4 = (NPIX / 4) / EB;  // 1984

    init_k<<<EG, EB>>>();

    float mu = 0.1f;                  // MU1 == MU2 at every step (same init, same rho)
    pre0_k<<<EG, EB>>>(Y, mu);
    solve_k<<<NIMG, 256, SM_TOTAL>>>(outp, 0, mu, mu);

    for (int t = 1; t < ITERS; t++) {
        float mup = mu;
        mu = mu * 1.05f;              // matches reference fp32 mu update
        fused4_k<<<EG4, EB>>>(Y, Wt, mup, mu, (t - 1) & 1);
        solve_k<<<NIMG, 256, SM_TOTAL>>>(outp, (t == ITERS - 1) ? 1 : 0, mu, mu);
    }
}

// round 14
// speedup vs baseline: 3.7640x; 1.6206x over previous
#include <cuda_runtime.h>
#include <cuda_bf16.h>
#include <math.h>

// Problem constants: shape (4, 31, 128, 128) fp32
#define HW      128
#define IPIX    (HW * HW)          // 16384
#define NIMG    124                // 4*31
#define NPIX    (NIMG * IPIX)      // 2031616
#define LAM_C   0.1f
#define PBB     272                // bf16 tile pitch bytes (136 elems)
#define TILE    (HW * PBB)         // 34816 bytes per bf16 tile

typedef unsigned int u32;

// ---------------- persistent device state (no allocations allowed) ----------------
// S21 = G21' + mu_next*Uh  (combined dual state; S22 likewise). G1 in-place.
__device__ float d_G1[NPIX];
__device__ float d_S21[2][NPIX];
__device__ float d_S22[2][NPIX];
__device__ float d_lam[HW];              // 2 - 2cos(2*pi*k/128)
__device__ __nv_bfloat16 d_Hh[IPIX];     // Hartley matrix hi-bf16, row-major
__device__ __nv_bfloat16 d_Hl[IPIX];     // lo residual

__device__ __forceinline__ float shrinkf(float x, float t) {
    float m = fabsf(x) - t;
    m = m > 0.f ? m : 0.f;
    return copysignf(m, x);
}

// ---------------- init: build H hi/lo bf16 + lambda ----------------
__global__ void init_k() {
    int idx = blockIdx.x * blockDim.x + threadIdx.x;
    if (idx < IPIX) {
        int a = idx >> 7, b = idx & 127;
        int t = (a * b) & 127;                        // cas is 2*pi periodic
        double ang = (double)t * 0.04908738521234052; // 2*pi/128
        double s = sin(ang), c = cos(ang);
        float v = (float)((s + c) * 0.08838834764831845); // 1/sqrt(128)
        __nv_bfloat16 h = __float2bfloat16(v);
        __nv_bfloat16 l = __float2bfloat16(v - __bfloat162float(h));
        d_Hh[idx] = h;
        d_Hl[idx] = l;
    }
    if (idx < HW) {
        double ang = (double)idx * 0.04908738521234052;
        d_lam[idx] = (float)(2.0 - 2.0 * cos(ang));
    }
}

// ================= mma.sync bf16-split machinery (proven R12) =================

__device__ __forceinline__ u32 smem_u32(const void* p) {
    u32 a;
    asm("{ .reg .u64 t; cvta.to.shared.u64 t, %1; cvt.u32.u64 %0, t; }" : "=r"(a) : "l"(p));
    return a;
}

__device__ __forceinline__ void ldm4(u32 addr, u32 r[4]) {
    asm volatile("ldmatrix.sync.aligned.m8n8.x4.shared.b16 {%0,%1,%2,%3}, [%4];"
        : "=r"(r[0]), "=r"(r[1]), "=r"(r[2]), "=r"(r[3]) : "r"(addr));
}

__device__ __forceinline__ void mma_bf16(float acc[4], const u32 a[4], u32 b0, u32 b1) {
    asm volatile("mma.sync.aligned.m16n8k16.row.col.f32.bf16.bf16.f32 "
        "{%0,%1,%2,%3}, {%4,%5,%6,%7}, {%8,%9}, {%0,%1,%2,%3};"
        : "+f"(acc[0]), "+f"(acc[1]), "+f"(acc[2]), "+f"(acc[3])
        : "r"(a[0]), "r"(a[1]), "r"(a[2]), "r"(a[3]), "r"(b0), "r"(b1));
}

// split two fp32 into packed bf16 hi + packed bf16 lo (elem0 in low half)
__device__ __forceinline__ void split2(float c0, float c1, u32& hi, u32& lo) {
    asm("cvt.rn.bf16x2.f32 %0, %1, %2;" : "=r"(hi) : "f"(c1), "f"(c0));
    float f0 = __uint_as_float(hi << 16);
    float f1 = __uint_as_float(hi & 0xFFFF0000u);
    float l0 = c0 - f0, l1 = c1 - f1;
    asm("cvt.rn.bf16x2.f32 %0, %1, %2;" : "=r"(lo) : "f"(l1), "f"(l0));
}

// One NT stage: acc[16][4] = (Hh+Hl) * (Bh+Bl)^T  (3-term split, fp32 accum).
__device__ __forceinline__ void gemm_stage(u32 Hh_a, u32 Hl_a, u32 Bh_a, u32 Bl_a,
                                           float acc[16][4], int lane, int wid) {
#pragma unroll
    for (int i = 0; i < 16; i++)
#pragma unroll
        for (int j = 0; j < 4; j++) acc[i][j] = 0.f;

    int q = lane >> 3, r = lane & 7;
    u32 aoff = (u32)((wid * 16 + (q & 1) * 8 + r) * PBB + (q >> 1) * 16);
    u32 boff = (u32)(((q >> 1) * 8 + r) * PBB + (q & 1) * 16);

#pragma unroll 1
    for (int ks = 0; ks < 8; ks++) {
        u32 ah[4], al[4];
        ldm4(Hh_a + aoff + ks * 32, ah);
        ldm4(Hl_a + aoff + ks * 32, al);
#pragma unroll
        for (int jt = 0; jt < 8; jt++) {
            u32 bh[4], bl[4];
            u32 ba = boff + (u32)(jt * 16 * PBB) + ks * 32;
            ldm4(Bh_a + ba, bh);
            ldm4(Bl_a + ba, bl);
            mma_bf16(acc[2 * jt],     ah, bh[0], bh[1]);
            mma_bf16(acc[2 * jt + 1], ah, bh[2], bh[3]);
            mma_bf16(acc[2 * jt],     ah, bl[0], bl[1]);
            mma_bf16(acc[2 * jt + 1], ah, bl[2], bl[3]);
            mma_bf16(acc[2 * jt],     al, bh[0], bh[1]);
            mma_bf16(acc[2 * jt + 1], al, bh[2], bh[3]);
        }
    }
}

// store acc as hi/lo bf16 tiles, row-major pitch PBB
__device__ __forceinline__ void store_tile(char* dh, char* dl, float acc[16][4],
                                           int lane, int wid) {
    int g = lane >> 2, t = lane & 3;
    int row0 = wid * 16 + g;
#pragma unroll
    for (int nt = 0; nt < 16; nt++) {
        int colb = (nt * 8 + t * 2) * 2;
        u32 hi, lo;
        split2(acc[nt][0], acc[nt][1], hi, lo);
        *(u32*)(dh + row0 * PBB + colb) = hi;
        *(u32*)(dl + row0 * PBB + colb) = lo;
        split2(acc[nt][2], acc[nt][3], hi, lo);
        *(u32*)(dh + (row0 + 8) * PBB + colb) = hi;
        *(u32*)(dl + (row0 + 8) * PBB + colb) = lo;
    }
}

// ---------------- in-CTA elementwise: post of body k + pre of body k+1 ----------------
// Reads Z from SMEM (Zf), state from gmem (L2-resident), writes new state + R bf16 tiles.
// first=true: pre-loop init (Z=X=Y, G=0, mup must be 0).
__device__ __forceinline__ void elem_update(
    int base, int tid, const float* Zf, char* Rh, char* Rl,
    const float* __restrict__ Y, const float* __restrict__ Wt,
    float mup, float muc, int rd, int wr, bool first)
{
    const float* __restrict__ S21o = d_S21[rd];
    const float* __restrict__ S22o = d_S22[rd];
    float* __restrict__ S21n = d_S21[wr];
    float* __restrict__ S22n = d_S22[wr];
    float thr  = LAM_C / muc;
    float inv2 = 1.0f / muc;
    float4 zero4 = make_float4(0.f, 0.f, 0.f, 0.f);

#pragma unroll 2
    for (int e = 0; e < 16; e++) {
        int q = e * 256 + tid;
        int i = q >> 5, j0 = (q & 31) * 4;
        int row = i * HW;
        int p = base + row + j0;
        int jw = (j0 + 127) & 127, je = (j0 + 4) & 127;
        int in_ = (i + 127) & 127, is = (i + 1) & 127;
        int ps = base + is * HW + j0;

        float4 zc4 = *(const float4*)&Zf[row + j0];
        float4 zn4 = *(const float4*)&Zf[in_ * HW + j0];
        float4 zs4 = *(const float4*)&Zf[is * HW + j0];
        float  zw  = Zf[row + jw];
        float  ze  = Zf[row + je];
        float4 y4  = *(const float4*)&Y[p];
        float4 w4  = *(const float4*)&Wt[p];
        float4 g14  = first ? zero4 : *(const float4*)&d_G1[p];
        float4 s21c = first ? zero4 : *(const float4*)&S21o[p];
        float4 s22c = first ? zero4 : *(const float4*)&S22o[p];
        float4 s22s = first ? zero4 : *(const float4*)&S22o[ps];
        float  s21e = first ? 0.f   : S21o[base + row + je];

        float z[4]  = {zc4.x, zc4.y, zc4.z, zc4.w};
        float zn[4] = {zn4.x, zn4.y, zn4.z, zn4.w};
        float zs[4] = {zs4.x, zs4.y, zs4.z, zs4.w};
        float y[4]  = {y4.x, y4.y, y4.z, y4.w};
        float w[4]  = {w4.x, w4.y, w4.z, w4.w};
        float g1[4] = {g14.x, g14.y, g14.z, g14.w};
        float s21a[5] = {s21c.x, s21c.y, s21c.z, s21c.w, s21e};
        float s22a[4] = {s22c.x, s22c.y, s22c.z, s22c.w};
        float s22sa[4] = {s22s.x, s22s.y, s22s.z, s22s.w};

        float dh[5];
        dh[0] = z[0] - zw;
        dh[1] = z[1] - z[0];
        dh[2] = z[2] - z[1];
        dh[3] = z[3] - z[2];
        dh[4] = ze - z[3];

        float S21v[5];
#pragma unroll
        for (int t = 0; t < 5; t++) {
            float g21 = s21a[t] - mup * dh[t];
            float uh  = shrinkf(dh[t] - g21 * inv2, thr);
            S21v[t] = g21 + muc * uh;
        }

        float4 outG1, outS21, outS22, outR;
        float* pG1  = (float*)&outG1;
        float* pS21 = (float*)&outS21;
        float* pS22 = (float*)&outS22;
        float* pR   = (float*)&outR;

#pragma unroll
        for (int t = 0; t < 4; t++) {
            float dv   = z[t] - zn[t];
            float dv_s = zs[t] - z[t];
            float g22  = s22a[t]  - mup * dv;
            float g22s = s22sa[t] - mup * dv_s;
            float uv   = shrinkf(dv   - g22  * inv2, thr);
            float uv_s = shrinkf(dv_s - g22s * inv2, thr);
            float S22v  = g22  + muc * uv;
            float S22sv = g22s + muc * uv_s;

            float xn  = first ? y[t]
                      : __fdividef(w[t] * y[t] + mup * z[t] - g1[t], w[t] + mup);
            float g1n = g1[t] + mup * (xn - z[t]);

            pG1[t]  = g1n;
            pS21[t] = S21v[t];
            pS22[t] = S22v;
            pR[t]   = muc * xn + g1n + (S21v[t] - S21v[t + 1]) + (S22v - S22sv);
        }

        *(float4*)&d_G1[p] = outG1;
        *(float4*)&S21n[p] = outS21;
        *(float4*)&S22n[p] = outS22;

        u32 hi, lo;
        split2(pR[0], pR[1], hi, lo);
        *(u32*)(Rh + i * PBB + j0 * 2)     = hi;
        *(u32*)(Rl + i * PBB + j0 * 2)     = lo;
        split2(pR[2], pR[3], hi, lo);
        *(u32*)(Rh + i * PBB + j0 * 2 + 4) = hi;
        *(u32*)(Rl + i * PBB + j0 * 2 + 4) = lo;
    }
}

// SMEM: lam 512B, tiles Hh, Hl, T0h, T0l, T1h, T1l. Z fp32 overlays T1h+T1l.
#define SM_TOTAL (512 + 6 * TILE)   // 209408

// ---------------- persistent per-image kernel: all 20 iterations ----------------
__global__ void __launch_bounds__(256, 1)
solve_p(const float* __restrict__ Y, const float* __restrict__ Wt,
        float* __restrict__ outp) {
    extern __shared__ char smc[];
    float* lamS = (float*)smc;
    char* Hh  = smc + 512;
    char* Hl  = Hh + TILE;
    char* T0h = Hl + TILE;
    char* T0l = T0h + TILE;
    char* T1h = T0l + TILE;
    char* T1l = T1h + TILE;
    float* Zf = (float*)T1h;                 // 64KB fp32 Z overlay (dead-M3 region)

    int tid = threadIdx.x;
    int wid = tid >> 5, lane = tid & 31;
    int base = blockIdx.x * IPIX;

    // load H tiles + lam + Y image -> Zf
    {
        const int4* sh = (const int4*)d_Hh;
        const int4* sl = (const int4*)d_Hl;
        for (int i = tid; i < 2048; i += 256) {
            int row = i >> 4, c = i & 15;
            *(int4*)(Hh + row * PBB + c * 16) = sh[i];
            *(int4*)(Hl + row * PBB + c * 16) = sl[i];
        }
        if (tid < HW) lamS[tid] = d_lam[tid];
        const float4* Yg = (const float4*)(Y + base);
        float4* Zv = (float4*)Zf;
        for (int i = tid; i < IPIX / 4; i += 256) Zv[i] = Yg[i];
    }
    __syncthreads();

    float mu = 0.1f;                         // MU1 == MU2 throughout
    // init: body-1 pre (Z=X=Y, G=0): writes S side 0, G1=0, R tiles -> T0
    elem_update(base, tid, Zf, T0h, T0l, Y, Wt, 0.f, mu, 0, 0, true);
    __syncthreads();

    u32 Hh_a = smem_u32(Hh), Hl_a = smem_u32(Hl);
    u32 T0h_a = smem_u32(T0h), T0l_a = smem_u32(T0l);
    u32 T1h_a = smem_u32(T1h), T1l_a = smem_u32(T1l);

    float acc[16][4];
    int g = lane >> 2, t = lane & 3;
    int row0 = wid * 16 + g;

    for (int k = 1; k <= 20; k++) {
        // Stage 1: M1 = H * R^T -> T1
        gemm_stage(Hh_a, Hl_a, T0h_a, T0l_a, acc, lane, wid);
        store_tile(T1h, T1l, acc, lane, wid);
        __syncthreads();

        // Stage 2: M2 = H * M1^T; divide by symmetric denom -> T0
        gemm_stage(Hh_a, Hl_a, T1h_a, T1l_a, acc, lane, wid);
        {
            float la0 = lamS[row0], la1 = lamS[row0 + 8];
#pragma unroll
            for (int nt = 0; nt < 16; nt++) {
                int col = nt * 8 + t * 2;
                float lb0 = lamS[col], lb1 = lamS[col + 1];
                acc[nt][0] = __fdividef(acc[nt][0], mu + mu * (la0 + lb0));
                acc[nt][1] = __fdividef(acc[nt][1], mu + mu * (la0 + lb1));
                acc[nt][2] = __fdividef(acc[nt][2], mu + mu * (la1 + lb0));
                acc[nt][3] = __fdividef(acc[nt][3], mu + mu * (la1 + lb1));
            }
        }
        store_tile(T0h, T0l, acc, lane, wid);
        __syncthreads();

        // Stage 3: M3 = H * M2s^T -> T1
        gemm_stage(Hh_a, Hl_a, T0h_a, T0l_a, acc, lane, wid);
        store_tile(T1h, T1l, acc, lane, wid);
        __syncthreads();

        // Stage 4: Z = H * M3^T
        gemm_stage(Hh_a, Hl_a, T1h_a, T1l_a, acc, lane, wid);

        if (k == 20) {
            float* dst = outp + base;
#pragma unroll
            for (int nt = 0; nt < 16; nt++) {
                int col = nt * 8 + t * 2;
                *(float2*)&dst[row0 * HW + col]       = make_float2(acc[nt][0], acc[nt][1]);
                *(float2*)&dst[(row0 + 8) * HW + col] = make_float2(acc[nt][2], acc[nt][3]);
            }
            return;
        }

        __syncthreads();                      // all T1 ldmatrix reads complete
        // Z -> SMEM overlay (T1 region)
#pragma unroll
        for (int nt = 0; nt < 16; nt++) {
            int col = nt * 8 + t * 2;
            *(float2*)&Zf[row0 * HW + col]       = make_float2(acc[nt][0], acc[nt][1]);
            *(float2*)&Zf[(row0 + 8) * HW + col] = make_float2(acc[nt][2], acc[nt][3]);
        }
        __syncthreads();

        float mup = mu;
        mu = mu * 1.05f;                      // matches reference fp32 mu chain
        elem_update(base, tid, Zf, T0h, T0l, Y, Wt, mup, mu, (k - 1) & 1, k & 1, false);
        __syncthreads();
    }
}

// ---------------- launcher ----------------
extern "C" void kernel_launch(void* const* d_in, const int* in_sizes, int n_in,
                              void* d_out, int out_size) {
    const float* Y  = (const float*)d_in[0];
    const float* Wt = (const float*)d_in[1];
    float* outp = (float*)d_out;
    (void)in_sizes; (void)n_in; (void)out_size;

    cudaFuncSetAttribute(solve_p, cudaFuncAttributeMaxDynamicSharedMemorySize, SM_TOTAL);

    init_k<<<64, 256>>>();                       // build H hi/lo + lambda
    solve_p<<<NIMG, 256, SM_TOTAL>>>(Y, Wt, outp);
}

// round 16
// speedup vs baseline: 3.8891x; 1.0332x over previous
#include <cuda_runtime.h>
#include <cuda_bf16.h>
#include <math.h>

// Problem constants: shape (4, 31, 128, 128) fp32
#define HW      128
#define IPIX    (HW * HW)          // 16384
#define NIMG    124                // 4*31
#define NPIX    (NIMG * IPIX)      // 2031616
#define LAM_C   0.1f
#define PBB     272                // bf16 tile pitch bytes (136 elems)
#define TILE    (HW * PBB)         // 34816 bytes per bf16 tile
#define NT      512                // threads per CTA (16 warps)

typedef unsigned int u32;

// ---------------- persistent device state (no allocations allowed) ----------------
// S21 = G21' + mu_next*Uh  (combined dual state; S22 likewise). G1 in-place.
__device__ float d_G1[NPIX];
__device__ float d_S21[2][NPIX];
__device__ float d_S22[2][NPIX];
__device__ float d_lam[HW];              // 2 - 2cos(2*pi*k/128)
__device__ __nv_bfloat16 d_Hh[IPIX];     // Hartley matrix hi-bf16, row-major
__device__ __nv_bfloat16 d_Hl[IPIX];     // lo residual

__device__ __forceinline__ float shrinkf(float x, float t) {
    float m = fabsf(x) - t;
    m = m > 0.f ? m : 0.f;
    return copysignf(m, x);
}

// ---------------- init: build H hi/lo bf16 + lambda ----------------
__global__ void init_k() {
    int idx = blockIdx.x * blockDim.x + threadIdx.x;
    if (idx < IPIX) {
        int a = idx >> 7, b = idx & 127;
        int t = (a * b) & 127;                        // cas is 2*pi periodic
        double ang = (double)t * 0.04908738521234052; // 2*pi/128
        double s = sin(ang), c = cos(ang);
        float v = (float)((s + c) * 0.08838834764831845); // 1/sqrt(128)
        __nv_bfloat16 h = __float2bfloat16(v);
        __nv_bfloat16 l = __float2bfloat16(v - __bfloat162float(h));
        d_Hh[idx] = h;
        d_Hl[idx] = l;
    }
    if (idx < HW) {
        double ang = (double)idx * 0.04908738521234052;
        d_lam[idx] = (float)(2.0 - 2.0 * cos(ang));
    }
}

// ================= mma.sync bf16-split machinery =================

__device__ __forceinline__ u32 smem_u32(const void* p) {
    u32 a;
    asm("{ .reg .u64 t; cvta.to.shared.u64 t, %1; cvt.u32.u64 %0, t; }" : "=r"(a) : "l"(p));
    return a;
}

__device__ __forceinline__ void ldm4(u32 addr, u32 r[4]) {
    asm volatile("ldmatrix.sync.aligned.m8n8.x4.shared.b16 {%0,%1,%2,%3}, [%4];"
        : "=r"(r[0]), "=r"(r[1]), "=r"(r[2]), "=r"(r[3]) : "r"(addr));
}

__device__ __forceinline__ void mma_bf16(float acc[4], const u32 a[4], u32 b0, u32 b1) {
    asm volatile("mma.sync.aligned.m16n8k16.row.col.f32.bf16.bf16.f32 "
        "{%0,%1,%2,%3}, {%4,%5,%6,%7}, {%8,%9}, {%0,%1,%2,%3};"
        : "+f"(acc[0]), "+f"(acc[1]), "+f"(acc[2]), "+f"(acc[3])
        : "r"(a[0]), "r"(a[1]), "r"(a[2]), "r"(a[3]), "r"(b0), "r"(b1));
}

// split two fp32 into packed bf16 hi + packed bf16 lo (elem0 in low half)
__device__ __forceinline__ void split2(float c0, float c1, u32& hi, u32& lo) {
    asm("cvt.rn.bf16x2.f32 %0, %1, %2;" : "=r"(hi) : "f"(c1), "f"(c0));
    float f0 = __uint_as_float(hi << 16);
    float f1 = __uint_as_float(hi & 0xFFFF0000u);
    float l0 = c0 - f0, l1 = c1 - f1;
    asm("cvt.rn.bf16x2.f32 %0, %1, %2;" : "=r"(lo) : "f"(l1), "f"(l0));
}

// One NT stage slice: acc[8][4] = (Hh+Hl)[mrow:+16] * (Bh+Bl)[nhalf*64:+64]^T
// (3-term split, fp32 accum). All operands row-major pitch PBB.
__device__ __forceinline__ void gemm_stage(u32 Hh_a, u32 Hl_a, u32 Bh_a, u32 Bl_a,
                                           float acc[8][4], int lane, int mrow, int nhalf) {
#pragma unroll
    for (int i = 0; i < 8; i++)
#pragma unroll
        for (int j = 0; j < 4; j++) acc[i][j] = 0.f;

    int q = lane >> 3, r = lane & 7;
    u32 aoff = (u32)((mrow + (q & 1) * 8 + r) * PBB + (q >> 1) * 16);
    u32 boff = (u32)((nhalf * 64 + (q >> 1) * 8 + r) * PBB + (q & 1) * 16);

#pragma unroll 1
    for (int ks = 0; ks < 8; ks++) {
        u32 ah[4], al[4];
        ldm4(Hh_a + aoff + ks * 32, ah);
        ldm4(Hl_a + aoff + ks * 32, al);
#pragma unroll
        for (int jt = 0; jt < 4; jt++) {
            u32 bh[4], bl[4];
            u32 ba = boff + (u32)(jt * 16 * PBB) + ks * 32;
            ldm4(Bh_a + ba, bh);
            ldm4(Bl_a + ba, bl);
            mma_bf16(acc[2 * jt],     ah, bh[0], bh[1]);
            mma_bf16(acc[2 * jt + 1], ah, bh[2], bh[3]);
            mma_bf16(acc[2 * jt],     ah, bl[0], bl[1]);
            mma_bf16(acc[2 * jt + 1], ah, bl[2], bl[3]);
            mma_bf16(acc[2 * jt],     al, bh[0], bh[1]);
            mma_bf16(acc[2 * jt + 1], al, bh[2], bh[3]);
        }
    }
}

// store acc slice as hi/lo bf16 tiles, row-major pitch PBB
__device__ __forceinline__ void store_tile(char* dh, char* dl, float acc[8][4],
                                           int lane, int mrow, int nhalf) {
    int g = lane >> 2, t = lane & 3;
    int row0 = mrow + g;
#pragma unroll
    for (int nt = 0; nt < 8; nt++) {
        int colb = (nhalf * 64 + nt * 8 + t * 2) * 2;
        u32 hi, lo;
        split2(acc[nt][0], acc[nt][1], hi, lo);
        *(u32*)(dh + row0 * PBB + colb) = hi;
        *(u32*)(dl + row0 * PBB + colb) = lo;
        split2(acc[nt][2], acc[nt][3], hi, lo);
        *(u32*)(dh + (row0 + 8) * PBB + colb) = hi;
        *(u32*)(dl + (row0 + 8) * PBB + colb) = lo;
    }
}

// ---------------- in-CTA elementwise: post of body k + pre of body k+1 ----------------
__device__ __forceinline__ void elem_update(
    int base, int tid, const float* Zf, char* Rh, char* Rl,
    const float* __restrict__ Y, const float* __restrict__ Wt,
    float mup, float muc, int rd, int wr, bool first)
{
    const float* __restrict__ S21o = d_S21[rd];
    const float* __restrict__ S22o = d_S22[rd];
    float* __restrict__ S21n = d_S21[wr];
    float* __restrict__ S22n = d_S22[wr];
    float thr  = LAM_C / muc;
    float inv2 = 1.0f / muc;
    float4 zero4 = make_float4(0.f, 0.f, 0.f, 0.f);

#pragma unroll 2
    for (int e = 0; e < 8; e++) {
        int q = e * NT + tid;
        int i = q >> 5, j0 = (q & 31) * 4;
        int row = i * HW;
        int p = base + row + j0;
        int jw = (j0 + 127) & 127, je = (j0 + 4) & 127;
        int in_ = (i + 127) & 127, is = (i + 1) & 127;
        int ps = base + is * HW + j0;

        float4 zc4 = *(const float4*)&Zf[row + j0];
        float4 zn4 = *(const float4*)&Zf[in_ * HW + j0];
        float4 zs4 = *(const float4*)&Zf[is * HW + j0];
        float  zw  = Zf[row + jw];
        float  ze  = Zf[row + je];
        float4 y4  = *(const float4*)&Y[p];
        float4 w4  = *(const float4*)&Wt[p];
        float4 g14  = first ? zero4 : *(const float4*)&d_G1[p];
        float4 s21c = first ? zero4 : *(const float4*)&S21o[p];
        float4 s22c = first ? zero4 : *(const float4*)&S22o[p];
        float4 s22s = first ? zero4 : *(const float4*)&S22o[ps];
        float  s21e = first ? 0.f   : S21o[base + row + je];

        float z[4]  = {zc4.x, zc4.y, zc4.z, zc4.w};
        float zn[4] = {zn4.x, zn4.y, zn4.z, zn4.w};
        float zs[4] = {zs4.x, zs4.y, zs4.z, zs4.w};
        float y[4]  = {y4.x, y4.y, y4.z, y4.w};
        float w[4]  = {w4.x, w4.y, w4.z, w4.w};
        float g1[4] = {g14.x, g14.y, g14.z, g14.w};
        float s21a[5] = {s21c.x, s21c.y, s21c.z, s21c.w, s21e};
        float s22a[4] = {s22c.x, s22c.y, s22c.z, s22c.w};
        float s22sa[4] = {s22s.x, s22s.y, s22s.z, s22s.w};

        float dh[5];
        dh[0] = z[0] - zw;
        dh[1] = z[1] - z[0];
        dh[2] = z[2] - z[1];
        dh[3] = z[3] - z[2];
        dh[4] = ze - z[3];

        float S21v[5];
#pragma unroll
        for (int t = 0; t < 5; t++) {
            float g21 = s21a[t] - mup * dh[t];
            float uh  = shrinkf(dh[t] - g21 * inv2, thr);
            S21v[t] = g21 + muc * uh;
        }

        float4 outG1, outS21, outS22, outR;
        float* pG1  = (float*)&outG1;
        float* pS21 = (float*)&outS21;
        float* pS22 = (float*)&outS22;
        float* pR   = (float*)&outR;

#pragma unroll
        for (int t = 0; t < 4; t++) {
            float dv   = z[t] - zn[t];
            float dv_s = zs[t] - z[t];
            float g22  = s22a[t]  - mup * dv;
            float g22s = s22sa[t] - mup * dv_s;
            float uv   = shrinkf(dv   - g22  * inv2, thr);
            float uv_s = shrinkf(dv_s - g22s * inv2, thr);
            float S22v  = g22  + muc * uv;
            float S22sv = g22s + muc * uv_s;

            float xn  = first ? y[t]
                      : __fdividef(w[t] * y[t] + mup * z[t] - g1[t], w[t] + mup);
            float g1n = g1[t] + mup * (xn - z[t]);

            pG1[t]  = g1n;
            pS21[t] = S21v[t];
            pS22[t] = S22v;
            pR[t]   = muc * xn + g1n + (S21v[t] - S21v[t + 1]) + (S22v - S22sv);
        }

        *(float4*)&d_G1[p] = outG1;
        *(float4*)&S21n[p] = outS21;
        *(float4*)&S22n[p] = outS22;

        u32 hi, lo;
        split2(pR[0], pR[1], hi, lo);
        *(u32*)(Rh + i * PBB + j0 * 2)     = hi;
        *(u32*)(Rl + i * PBB + j0 * 2)     = lo;
        split2(pR[2], pR[3], hi, lo);
        *(u32*)(Rh + i * PBB + j0 * 2 + 4) = hi;
        *(u32*)(Rl + i * PBB + j0 * 2 + 4) = lo;
    }
}

// SMEM: lam 512B, tiles Hh, Hl, T0h, T0l, T1h, T1l. Z fp32 overlays T1h+T1l.
#define SM_TOTAL (512 + 6 * TILE)   // 209408

// ---------------- persistent per-image kernel: all 20 iterations ----------------
__global__ void __launch_bounds__(NT, 1)
solve_p(const float* __restrict__ Y, const float* __restrict__ Wt,
        float* __restrict__ outp) {
    extern __shared__ char smc[];
    float* lamS = (float*)smc;
    char* Hh  = smc + 512;
    char* Hl  = Hh + TILE;
    char* T0h = Hl + TILE;
    char* T0l = T0h + TILE;
    char* T1h = T0l + TILE;
    char* T1l = T1h + TILE;
    float* Zf = (float*)T1h;                 // 64KB fp32 Z overlay (dead-M3 region)

    int tid = threadIdx.x;
    int wid = tid >> 5, lane = tid & 31;
    int mrow = (wid & 7) * 16;               // warp's M rows
    int nhalf = wid >> 3;                    // warp's N half (0/1)
    int base = blockIdx.x * IPIX;

    // load H tiles + lam + Y image -> Zf
    {
        const int4* sh = (const int4*)d_Hh;
        const int4* sl = (const int4*)d_Hl;
        for (int i = tid; i < 2048; i += NT) {
            int row = i >> 4, c = i & 15;
            *(int4*)(Hh + row * PBB + c * 16) = sh[i];
            *(int4*)(Hl + row * PBB + c * 16) = sl[i];
        }
        if (tid < HW) lamS[tid] = d_lam[tid];
        const float4* Yg = (const float4*)(Y + base);
        float4* Zv = (float4*)Zf;
        for (int i = tid; i < IPIX / 4; i += NT) Zv[i] = Yg[i];
    }
    __syncthreads();

    float mu = 0.1f;                         // MU1 == MU2 throughout
    // init: body-1 pre (Z=X=Y, G=0): writes S side 0, G1=0, R tiles -> T0
    elem_update(base, tid, Zf, T0h, T0l, Y, Wt, 0.f, mu, 0, 0, true);
    __syncthreads();

    u32 Hh_a = smem_u32(Hh), Hl_a = smem_u32(Hl);
    u32 T0h_a = smem_u32(T0h), T0l_a = smem_u32(T0l);
    u32 T1h_a = smem_u32(T1h), T1l_a = smem_u32(T1l);

    float acc[8][4];
    int g = lane >> 2, t = lane & 3;
    int row0 = mrow + g;

    for (int k = 1; k <= 20; k++) {
        // Stage 1: M1 = H * R^T -> T1
        gemm_stage(Hh_a, Hl_a, T0h_a, T0l_a, acc, lane, mrow, nhalf);
        store_tile(T1h, T1l, acc, lane, mrow, nhalf);
        __syncthreads();

        // Stage 2: M2 = H * M1^T; divide by symmetric denom -> T0
        gemm_stage(Hh_a, Hl_a, T1h_a, T1l_a, acc, lane, mrow, nhalf);
        {
            float la0 = lamS[row0], la1 = lamS[row0 + 8];
#pragma unroll
            for (int nt = 0; nt < 8; nt++) {
                int col = nhalf * 64 + nt * 8 + t * 2;
                float lb0 = lamS[col], lb1 = lamS[col + 1];
                acc[nt][0] = __fdividef(acc[nt][0], mu + mu * (la0 + lb0));
                acc[nt][1] = __fdividef(acc[nt][1], mu + mu * (la0 + lb1));
                acc[nt][2] = __fdividef(acc[nt][2], mu + mu * (la1 + lb0));
                acc[nt][3] = __fdividef(acc[nt][3], mu + mu * (la1 + lb1));
            }
        }
        store_tile(T0h, T0l, acc, lane, mrow, nhalf);
        __syncthreads();

        // Stage 3: M3 = H * M2s^T -> T1
        gemm_stage(Hh_a, Hl_a, T0h_a, T0l_a, acc, lane, mrow, nhalf);
        store_tile(T1h, T1l, acc, lane, mrow, nhalf);
        __syncthreads();

        // Stage 4: Z = H * M3^T
        gemm_stage(Hh_a, Hl_a, T1h_a, T1l_a, acc, lane, mrow, nhalf);

        if (k == 20) {
            float* dst = outp + base;
#pragma unroll
            for (int nt = 0; nt < 8; nt++) {
                int col = nhalf * 64 + nt * 8 + t * 2;
                *(float2*)&dst[row0 * HW + col]       = make_float2(acc[nt][0], acc[nt][1]);
                *(float2*)&dst[(row0 + 8) * HW + col] = make_float2(acc[nt][2], acc[nt][3]);
            }
            return;
        }

        __syncthreads();                      // all T1 ldmatrix reads complete
        // Z -> SMEM overlay (T1 region)
#pragma unroll
        for (int nt = 0; nt < 8; nt++) {
            int col = nhalf * 64 + nt * 8 + t * 2;
            *(float2*)&Zf[row0 * HW + col]       = make_float2(acc[nt][0], acc[nt][1]);
            *(float2*)&Zf[(row0 + 8) * HW + col] = make_float2(acc[nt][2], acc[nt][3]);
        }
        __syncthreads();

        float mup = mu;
        mu = mu * 1.05f;                      // matches reference fp32 mu chain
        elem_update(base, tid, Zf, T0h, T0l, Y, Wt, mup, mu, (k - 1) & 1, k & 1, false);
        __syncthreads();
    }
}

// ---------------- launcher ----------------
extern "C" void kernel_launch(void* const* d_in, const int* in_sizes, int n_in,
                              void* d_out, int out_size) {
    const float* Y  = (const float*)d_in[0];
    const float* Wt = (const float*)d_in[1];
    float* outp = (float*)d_out;
    (void)in_sizes; (void)n_in; (void)out_size;

    cudaFuncSetAttribute(solve_p, cudaFuncAttributeMaxDynamicSharedMemorySize, SM_TOTAL);

    init_k<<<64, 256>>>();                       // build H hi/lo + lambda
    solve_p<<<NIMG, NT, SM_TOTAL>>>(Y, Wt, outp);
}

// round 17
// speedup vs baseline: 3.9644x; 1.0194x over previous
#include <cuda_runtime.h>
#include <cuda_bf16.h>
#include <math.h>

// Problem constants: shape (4, 31, 128, 128) fp32
#define HW      128
#define IPIX    (HW * HW)          // 16384
#define NIMG    124                // 4*31
#define NPIX    (NIMG * IPIX)      // 2031616
#define LAM_C   0.1f
#define PBB     272                // bf16 tile pitch bytes (136 elems)
#define TILE    (HW * PBB)         // 34816 bytes per bf16 tile
#define NT      512                // threads per CTA (16 warps)

typedef unsigned int u32;
typedef unsigned short u16;

// ---------------- persistent device state (no allocations allowed) ----------------
// S21 = G21' + mu_next*Uh  (combined dual state; S22 likewise). G1 in-place.
__device__ float d_G1[NPIX];
__device__ float d_S21[2][NPIX];
__device__ float d_S22[2][NPIX];
__device__ float d_lam[HW];              // 2 - 2cos(2*pi*k/128)
__device__ __nv_bfloat16 d_Hh[IPIX];     // Hartley matrix hi-bf16, row-major
__device__ __nv_bfloat16 d_Hl[IPIX];     // lo residual

__device__ __forceinline__ float shrinkf(float x, float t) {
    float m = fabsf(x) - t;
    m = m > 0.f ? m : 0.f;
    return copysignf(m, x);
}

// ---------------- init: build H hi/lo bf16 + lambda ----------------
__global__ void init_k() {
    int idx = blockIdx.x * blockDim.x + threadIdx.x;
    if (idx < IPIX) {
        int a = idx >> 7, b = idx & 127;
        int t = (a * b) & 127;                        // cas is 2*pi periodic
        double ang = (double)t * 0.04908738521234052; // 2*pi/128
        double s = sin(ang), c = cos(ang);
        float v = (float)((s + c) * 0.08838834764831845); // 1/sqrt(128)
        __nv_bfloat16 h = __float2bfloat16(v);
        __nv_bfloat16 l = __float2bfloat16(v - __bfloat162float(h));
        d_Hh[idx] = h;
        d_Hl[idx] = l;
    }
    if (idx < HW) {
        double ang = (double)idx * 0.04908738521234052;
        d_lam[idx] = (float)(2.0 - 2.0 * cos(ang));
    }
}

// ================= mma.sync bf16-split machinery =================

__device__ __forceinline__ u32 smem_u32(const void* p) {
    u32 a;
    asm("{ .reg .u64 t; cvta.to.shared.u64 t, %1; cvt.u32.u64 %0, t; }" : "=r"(a) : "l"(p));
    return a;
}

__device__ __forceinline__ void ldm4(u32 addr, u32 r[4]) {
    asm volatile("ldmatrix.sync.aligned.m8n8.x4.shared.b16 {%0,%1,%2,%3}, [%4];"
        : "=r"(r[0]), "=r"(r[1]), "=r"(r[2]), "=r"(r[3]) : "r"(addr));
}

__device__ __forceinline__ void mma_bf16(float acc[4], const u32 a[4], u32 b0, u32 b1) {
    asm volatile("mma.sync.aligned.m16n8k16.row.col.f32.bf16.bf16.f32 "
        "{%0,%1,%2,%3}, {%4,%5,%6,%7}, {%8,%9}, {%0,%1,%2,%3};"
        : "+f"(acc[0]), "+f"(acc[1]), "+f"(acc[2]), "+f"(acc[3])
        : "r"(a[0]), "r"(a[1]), "r"(a[2]), "r"(a[3]), "r"(b0), "r"(b1));
}

// split two fp32 into packed bf16 hi + packed bf16 lo (elem0 in low half)
__device__ __forceinline__ void split2(float c0, float c1, u32& hi, u32& lo) {
    asm("cvt.rn.bf16x2.f32 %0, %1, %2;" : "=r"(hi) : "f"(c1), "f"(c0));
    float f0 = __uint_as_float(hi << 16);
    float f1 = __uint_as_float(hi & 0xFFFF0000u);
    float l0 = c0 - f0, l1 = c1 - f1;
    asm("cvt.rn.bf16x2.f32 %0, %1, %2;" : "=r"(lo) : "f"(l1), "f"(l0));
}

// unpack bf16x2 pair to two fp32 (elem0 in low half)
__device__ __forceinline__ void upk_bf2(u32 v, float& a, float& b) {
    a = __uint_as_float(v << 16);
    b = __uint_as_float(v & 0xFFFF0000u);
}

// One stage slice: acc[8][4] = (Hh+Hl)[mq*32:+32] * (Bh+Bl)[nq*32:+32]^T
// (3-term split, fp32 accum). acc index = mt*4 + jt*2 + h8.
__device__ __forceinline__ void gemm_stage(u32 Hh_a, u32 Hl_a, u32 Bh_a, u32 Bl_a,
                                           float acc[8][4], int lane, int mq, int nq) {
#pragma unroll
    for (int i = 0; i < 8; i++)
#pragma unroll
        for (int j = 0; j < 4; j++) acc[i][j] = 0.f;

    int q = lane >> 3, r = lane & 7;
    u32 aoff0 = (u32)((mq * 32 + (q & 1) * 8 + r) * PBB + (q >> 1) * 16);
    u32 aoff1 = aoff0 + 16 * PBB;
    u32 boff0 = (u32)((nq * 32 + (q >> 1) * 8 + r) * PBB + (q & 1) * 16);
    u32 boff1 = boff0 + 16 * PBB;

#pragma unroll 1
    for (int ks = 0; ks < 8; ks++) {
        u32 kb = ks * 32;
        u32 ah0[4], ah1[4], al0[4], al1[4];
        u32 bh0[4], bh1[4], bl0[4], bl1[4];
        ldm4(Hh_a + aoff0 + kb, ah0);
        ldm4(Hh_a + aoff1 + kb, ah1);
        ldm4(Hl_a + aoff0 + kb, al0);
        ldm4(Hl_a + aoff1 + kb, al1);
        ldm4(Bh_a + boff0 + kb, bh0);
        ldm4(Bh_a + boff1 + kb, bh1);
        ldm4(Bl_a + boff0 + kb, bl0);
        ldm4(Bl_a + boff1 + kb, bl1);

        // mt=0
        mma_bf16(acc[0], ah0, bh0[0], bh0[1]);
        mma_bf16(acc[1], ah0, bh0[2], bh0[3]);
        mma_bf16(acc[2], ah0, bh1[0], bh1[1]);
        mma_bf16(acc[3], ah0, bh1[2], bh1[3]);
        mma_bf16(acc[0], ah0, bl0[0], bl0[1]);
        mma_bf16(acc[1], ah0, bl0[2], bl0[3]);
        mma_bf16(acc[2], ah0, bl1[0], bl1[1]);
        mma_bf16(acc[3], ah0, bl1[2], bl1[3]);
        mma_bf16(acc[0], al0, bh0[0], bh0[1]);
        mma_bf16(acc[1], al0, bh0[2], bh0[3]);
        mma_bf16(acc[2], al0, bh1[0], bh1[1]);
        mma_bf16(acc[3], al0, bh1[2], bh1[3]);
        // mt=1
        mma_bf16(acc[4], ah1, bh0[0], bh0[1]);
        mma_bf16(acc[5], ah1, bh0[2], bh0[3]);
        mma_bf16(acc[6], ah1, bh1[0], bh1[1]);
        mma_bf16(acc[7], ah1, bh1[2], bh1[3]);
        mma_bf16(acc[4], ah1, bl0[0], bl0[1]);
        mma_bf16(acc[5], ah1, bl0[2], bl0[3]);
        mma_bf16(acc[6], ah1, bl1[0], bl1[1]);
        mma_bf16(acc[7], ah1, bl1[2], bl1[3]);
        mma_bf16(acc[4], al1, bh0[0], bh0[1]);
        mma_bf16(acc[5], al1, bh0[2], bh0[3]);
        mma_bf16(acc[6], al1, bh1[0], bh1[1]);
        mma_bf16(acc[7], al1, bh1[2], bh1[3]);
    }
}

// store acc slice as hi/lo bf16 tiles, row-major pitch PBB
__device__ __forceinline__ void store_tile(char* dh, char* dl, float acc[8][4],
                                           int lane, int mq, int nq) {
    int g = lane >> 2, t = lane & 3;
#pragma unroll
    for (int mt = 0; mt < 2; mt++) {
        int row0 = mq * 32 + mt * 16 + g;
#pragma unroll
        for (int nn = 0; nn < 4; nn++) {            // nn = jt*2 + h8
            float* a = acc[mt * 4 + nn];
            int colb = (nq * 32 + nn * 8 + t * 2) * 2;
            u32 hi, lo;
            split2(a[0], a[1], hi, lo);
            *(u32*)(dh + row0 * PBB + colb) = hi;
            *(u32*)(dl + row0 * PBB + colb) = lo;
            split2(a[2], a[3], hi, lo);
            *(u32*)(dh + (row0 + 8) * PBB + colb) = hi;
            *(u32*)(dl + (row0 + 8) * PBB + colb) = lo;
        }
    }
}

// ---------------- in-CTA elementwise: post of body k + pre of body k+1 ----------------
// FIRST=true: Z=Y from gmem, state=0. Else Z reconstructed from hi/lo bf16 tiles.
template <bool FIRST>
__device__ __forceinline__ void elem_update(
    int base, int tid, const char* Zh, const char* Zl, char* Rh, char* Rl,
    const float* __restrict__ Y, const float* __restrict__ Wt,
    float mup, float muc, int rd, int wr)
{
    const float* __restrict__ S21o = d_S21[rd];
    const float* __restrict__ S22o = d_S22[rd];
    float* __restrict__ S21n = d_S21[wr];
    float* __restrict__ S22n = d_S22[wr];
    float thr  = LAM_C / muc;
    float inv2 = 1.0f / muc;
    float4 zero4 = make_float4(0.f, 0.f, 0.f, 0.f);

#pragma unroll 2
    for (int e = 0; e < 8; e++) {
        int q = e * NT + tid;
        int i = q >> 5, j0 = (q & 31) * 4;
        int row = i * HW;
        int p = base + row + j0;
        int jw = (j0 + 127) & 127, je = (j0 + 4) & 127;
        int in_ = (i + 127) & 127, is = (i + 1) & 127;
        int ps = base + is * HW + j0;

        float z[4], zn[4], zs[4], zw, ze;
        if (FIRST) {
            float4 zc4 = *(const float4*)&Y[p];
            float4 zn4 = *(const float4*)&Y[base + in_ * HW + j0];
            float4 zs4 = *(const float4*)&Y[ps];
            z[0] = zc4.x; z[1] = zc4.y; z[2] = zc4.z; z[3] = zc4.w;
            zn[0] = zn4.x; zn[1] = zn4.y; zn[2] = zn4.z; zn[3] = zn4.w;
            zs[0] = zs4.x; zs[1] = zs4.y; zs[2] = zs4.z; zs[3] = zs4.w;
            zw = Y[base + row + jw];
            ze = Y[base + row + je];
        } else {
            int ob = i * PBB + j0 * 2;
            int obn = in_ * PBB + j0 * 2;
            int obs = is * PBB + j0 * 2;
            u32 h01, h23, l01, l23;
            float a0, a1, b0, b1;
            h01 = *(const u32*)(Zh + ob); h23 = *(const u32*)(Zh + ob + 4);
            l01 = *(const u32*)(Zl + ob); l23 = *(const u32*)(Zl + ob + 4);
            upk_bf2(h01, a0, a1); upk_bf2(l01, b0, b1);
            z[0] = a0 + b0; z[1] = a1 + b1;
            upk_bf2(h23, a0, a1); upk_bf2(l23, b0, b1);
            z[2] = a0 + b0; z[3] = a1 + b1;
            h01 = *(const u32*)(Zh + obn); h23 = *(const u32*)(Zh + obn + 4);
            l01 = *(const u32*)(Zl + obn); l23 = *(const u32*)(Zl + obn + 4);
            upk_bf2(h01, a0, a1); upk_bf2(l01, b0, b1);
            zn[0] = a0 + b0; zn[1] = a1 + b1;
            upk_bf2(h23, a0, a1); upk_bf2(l23, b0, b1);
            zn[2] = a0 + b0; zn[3] = a1 + b1;
            h01 = *(const u32*)(Zh + obs); h23 = *(const u32*)(Zh + obs + 4);
            l01 = *(const u32*)(Zl + obs); l23 = *(const u32*)(Zl + obs + 4);
            upk_bf2(h01, a0, a1); upk_bf2(l01, b0, b1);
            zs[0] = a0 + b0; zs[1] = a1 + b1;
            upk_bf2(h23, a0, a1); upk_bf2(l23, b0, b1);
            zs[2] = a0 + b0; zs[3] = a1 + b1;
            u32 hw = *(const u16*)(Zh + i * PBB + jw * 2);
            u32 lw = *(const u16*)(Zl + i * PBB + jw * 2);
            zw = __uint_as_float(hw << 16) + __uint_as_float(lw << 16);
            u32 he = *(const u16*)(Zh + i * PBB + je * 2);
            u32 le = *(const u16*)(Zl + i * PBB + je * 2);
            ze = __uint_as_float(he << 16) + __uint_as_float(le << 16);
        }

        float4 y4  = *(const float4*)&Y[p];
        float4 w4  = *(const float4*)&Wt[p];
        float4 g14  = FIRST ? zero4 : *(const float4*)&d_G1[p];
        float4 s21c = FIRST ? zero4 : *(const float4*)&S21o[p];
        float4 s22c = FIRST ? zero4 : *(const float4*)&S22o[p];
        float4 s22s = FIRST ? zero4 : *(const float4*)&S22o[ps];
        float  s21e = FIRST ? 0.f   : S21o[base + row + je];

        float y[4]  = {y4.x, y4.y, y4.z, y4.w};
        float w[4]  = {w4.x, w4.y, w4.z, w4.w};
        float g1[4] = {g14.x, g14.y, g14.z, g14.w};
        float s21a[5] = {s21c.x, s21c.y, s21c.z, s21c.w, s21e};
        float s22a[4] = {s22c.x, s22c.y, s22c.z, s22c.w};
        float s22sa[4] = {s22s.x, s22s.y, s22s.z, s22s.w};

        float dh[5];
        dh[0] = z[0] - zw;
        dh[1] = z[1] - z[0];
        dh[2] = z[2] - z[1];
        dh[3] = z[3] - z[2];
        dh[4] = ze - z[3];

        float S21v[5];
#pragma unroll
        for (int t = 0; t < 5; t++) {
            float g21 = s21a[t] - mup * dh[t];
            float uh  = shrinkf(dh[t] - g21 * inv2, thr);
            S21v[t] = g21 + muc * uh;
        }

        float4 outG1, outS21, outS22, outR;
        float* pG1  = (float*)&outG1;
        float* pS21 = (float*)&outS21;
        float* pS22 = (float*)&outS22;
        float* pR   = (float*)&outR;

#pragma unroll
        for (int t = 0; t < 4; t++) {
            float dv   = z[t] - zn[t];
            float dv_s = zs[t] - z[t];
            float g22  = s22a[t]  - mup * dv;
            float g22s = s22sa[t] - mup * dv_s;
            float uv   = shrinkf(dv   - g22  * inv2, thr);
            float uv_s = shrinkf(dv_s - g22s * inv2, thr);
            float S22v  = g22  + muc * uv;
            float S22sv = g22s + muc * uv_s;

            float xn  = FIRST ? y[t]
                      : __fdividef(w[t] * y[t] + mup * z[t] - g1[t], w[t] + mup);
            float g1n = g1[t] + mup * (xn - z[t]);

            pG1[t]  = g1n;
            pS21[t] = S21v[t];
            pS22[t] = S22v;
            pR[t]   = muc * xn + g1n + (S21v[t] - S21v[t + 1]) + (S22v - S22sv);
        }

        *(float4*)&d_G1[p] = outG1;
        *(float4*)&S21n[p] = outS21;
        *(float4*)&S22n[p] = outS22;

        u32 hi, lo;
        split2(pR[0], pR[1], hi, lo);
        *(u32*)(Rh + i * PBB + j0 * 2)     = hi;
        *(u32*)(Rl + i * PBB + j0 * 2)     = lo;
        split2(pR[2], pR[3], hi, lo);
        *(u32*)(Rh + i * PBB + j0 * 2 + 4) = hi;
        *(u32*)(Rl + i * PBB + j0 * 2 + 4) = lo;
    }
}

// SMEM: lam 512B, tiles Hh, Hl, T0h, T0l, T1h, T1l.
#define SM_TOTAL (512 + 6 * TILE)   // 209408

// ---------------- persistent per-image kernel: all 20 iterations ----------------
__global__ void __launch_bounds__(NT, 1)
solve_p(const float* __restrict__ Y, const float* __restrict__ Wt,
        float* __restrict__ outp) {
    extern __shared__ char smc[];
    float* lamS = (float*)smc;
    char* Hh  = smc + 512;
    char* Hl  = Hh + TILE;
    char* Tah = Hl + TILE;       // buffer A (holds R at loop top)
    char* Tal = Tah + TILE;
    char* Tbh = Tal + TILE;      // buffer B
    char* Tbl = Tbh + TILE;

    int tid = threadIdx.x;
    int wid = tid >> 5, lane = tid & 31;
    int mq = wid & 3, nq = wid >> 2;       // 4x4 grid of 32x32 warp tiles
    int base = blockIdx.x * IPIX;

    // load H tiles + lam
    {
        const int4* sh = (const int4*)d_Hh;
        const int4* sl = (const int4*)d_Hl;
        for (int i = tid; i < 2048; i += NT) {
            int row = i >> 4, c = i & 15;
            *(int4*)(Hh + row * PBB + c * 16) = sh[i];
            *(int4*)(Hl + row * PBB + c * 16) = sl[i];
        }
        if (tid < HW) lamS[tid] = d_lam[tid];
    }
    __syncthreads();

    float mu = 0.1f;                         // MU1 == MU2 throughout
    // init: body-1 pre (Z=X=Y from gmem, G=0): writes state side 0, R tiles -> A
    elem_update<true>(base, tid, nullptr, nullptr, Tah, Tal, Y, Wt, 0.f, mu, 0, 0);
    __syncthreads();

    u32 Hh_a = smem_u32(Hh), Hl_a = smem_u32(Hl);
    u32 Tah_a = smem_u32(Tah), Tal_a = smem_u32(Tal);
    u32 Tbh_a = smem_u32(Tbh), Tbl_a = smem_u32(Tbl);

    float acc[8][4];
    int g = lane >> 2, t = lane & 3;

    for (int k = 1; k <= 20; k++) {
        // Stage 1: M1 = H * R^T : A -> B
        gemm_stage(Hh_a, Hl_a, Tah_a, Tal_a, acc, lane, mq, nq);
        store_tile(Tbh, Tbl, acc, lane, mq, nq);
        __syncthreads();

        // Stage 2: M2 = H * M1^T; divide by symmetric denom : B -> A
        gemm_stage(Hh_a, Hl_a, Tbh_a, Tbl_a, acc, lane, mq, nq);
        {
#pragma unroll
            for (int mt = 0; mt < 2; mt++) {
                int row0 = mq * 32 + mt * 16 + g;
                float la0 = lamS[row0], la1 = lamS[row0 + 8];
#pragma unroll
                for (int nn = 0; nn < 4; nn++) {
                    float* a = acc[mt * 4 + nn];
                    int col = nq * 32 + nn * 8 + t * 2;
                    float lb0 = lamS[col], lb1 = lamS[col + 1];
                    a[0] = __fdividef(a[0], mu + mu * (la0 + lb0));
                    a[1] = __fdividef(a[1], mu + mu * (la0 + lb1));
                    a[2] = __fdividef(a[2], mu + mu * (la1 + lb0));
                    a[3] = __fdividef(a[3], mu + mu * (la1 + lb1));
                }
            }
        }
        store_tile(Tah, Tal, acc, lane, mq, nq);
        __syncthreads();

        // Stage 3: M3 = H * M2s^T : A -> B
        gemm_stage(Hh_a, Hl_a, Tah_a, Tal_a, acc, lane, mq, nq);
        store_tile(Tbh, Tbl, acc, lane, mq, nq);
        __syncthreads();

        // Stage 4: Z = H * M3^T : B -> A (as hi/lo bf16), or gmem on last iter
        gemm_stage(Hh_a, Hl_a, Tbh_a, Tbl_a, acc, lane, mq, nq);

        if (k == 20) {
            float* dst = outp + base;
#pragma unroll
            for (int mt = 0; mt < 2; mt++) {
                int row0 = mq * 32 + mt * 16 + g;
#pragma unroll
                for (int nn = 0; nn < 4; nn++) {
                    float* a = acc[mt * 4 + nn];
                    int col = nq * 32 + nn * 8 + t * 2;
                    *(float2*)&dst[row0 * HW + col]       = make_float2(a[0], a[1]);
                    *(float2*)&dst[(row0 + 8) * HW + col] = make_float2(a[2], a[3]);
                }
            }
            return;
        }

        store_tile(Tah, Tal, acc, lane, mq, nq);   // Z -> A (M2s dead)
        __syncthreads();

        float mup = mu;
        mu = mu * 1.05f;                      // matches reference fp32 mu chain
        // elem: read Z from A, write R to B; then swap roles
        elem_update<false>(base, tid, Tah, Tal, Tbh, Tbl, Y, Wt,
                           mup, mu, (k - 1) & 1, k & 1);
        __syncthreads();

        { char* tmp = Tah; Tah = Tbh; Tbh = tmp; }
        { char* tmp = Tal; Tal = Tbl; Tbl = tmp; }
        { u32 tmp = Tah_a; Tah_a = Tbh_a; Tbh_a = tmp; }
        { u32 tmp = Tal_a; Tal_a = Tbl_a; Tbl_a = tmp; }
    }
}

// ---------------- launcher ----------------
extern "C" void kernel_launch(void* const* d_in, const int* in_sizes, int n_in,
                              void* d_out, int out_size) {
    const float* Y  = (const float*)d_in[0];
    const float* Wt = (const float*)d_in[1];
    float* outp = (float*)d_out;
    (void)in_sizes; (void)n_in; (void)out_size;

    cudaFuncSetAttribute(solve_p, cudaFuncAttributeMaxDynamicSharedMemorySize, SM_TOTAL);

    init_k<<<64, 256>>>();                       // build H hi/lo + lambda
    solve_p<<<NIMG, NT, SM_TOTAL>>>(Y, Wt, outp);
}